// round 2
// baseline (speedup 1.0000x reference)
#include <cuda_runtime.h>
#include <math.h>

#define BATCH 2048
#define NIN   512
#define NOUT  512

// ---------------- scratch (device globals; no runtime allocation) ----------------
__device__ float g_XP[8][BATCH][NIN];    // x planes            [blade][b][n]
__device__ float g_XR[8][BATCH][NIN];    // raw xr planes       [blade][b][n]
__device__ float g_ZP[44][BATCH][NIN];   // pair channels       [chan][b][n]
__device__ float g_OUTP[8][BATCH][NOUT]; // planar output       [blade][b][m]
__device__ float g_WR[4][NIN][NIN];      // w_right planes      [grade][m][n]
__device__ float g_WL[4][NOUT][NIN];     // w_left planes       [grade][m][n]
__device__ float g_WT[20][NOUT][NIN];    // weight planes       [path][m][n]

__constant__ int c_grade[8] = {0,1,1,1,2,2,2,3};

// per-output-blade channel tables: (A plane idx, B plane idx)
// A idx: 0..7 -> g_XP[idx]; 8..51 -> g_ZP[idx-8]
// B idx: 0..3 -> g_WL[idx]; 4..23 -> g_WT[idx-4]
__constant__ int c_nch[8] = {5,7,7,7,7,7,7,5};
__constant__ int c_aidx[8][7] = {
    {0, 8,16,30,44, 0, 0},
    {1, 9,17,20,31,34,45},
    {2,10,18,21,32,35,46},
    {3,11,19,22,33,36,47},
    {4,12,23,26,37,40,48},
    {5,13,24,27,38,41,49},
    {6,14,25,28,39,42,50},
    {7,15,29,43,51, 0, 0}
};
__constant__ int c_bidx[8][7] = {
    {0, 4, 8,14,20, 0, 0},
    {1, 5, 9,10,15,16,21},
    {1, 5, 9,10,15,16,21},
    {1, 5, 9,10,15,16,21},
    {2, 6,11,12,17,18,22},
    {2, 6,11,12,17,18,22},
    {2, 6,11,12,17,18,22},
    {3, 7,13,19,23, 0, 0}
};

__device__ __forceinline__ const float* a_plane(int idx) {
    return (idx < 8) ? &g_XP[idx][0][0] : &g_ZP[idx - 8][0][0];
}
__device__ __forceinline__ const float* b_plane(int idx) {
    return (idx < 4) ? &g_WL[idx][0][0] : &g_WT[idx - 4][0][0];
}

// ---------------- K0: transpose inputs into planes ----------------
__global__ void k0_prep(const float* __restrict__ x,
                        const float* __restrict__ weight,
                        const float* __restrict__ w_right,
                        const float* __restrict__ w_left) {
    int idx = blockIdx.x * blockDim.x + threadIdx.x;   // 0 .. 2048*512-1
    int b = idx >> 9;
    int n = idx & 511;

    float4 v0 = ((const float4*)x)[(size_t)idx * 2 + 0];
    float4 v1 = ((const float4*)x)[(size_t)idx * 2 + 1];
    g_XP[0][b][n] = v0.x; g_XP[1][b][n] = v0.y; g_XP[2][b][n] = v0.z; g_XP[3][b][n] = v0.w;
    g_XP[4][b][n] = v1.x; g_XP[5][b][n] = v1.y; g_XP[6][b][n] = v1.z; g_XP[7][b][n] = v1.w;

    if (b < NOUT) {
        int m = b;
        float4 wr = ((const float4*)w_right)[(size_t)m * NIN + n];
        g_WR[0][m][n] = wr.x; g_WR[1][m][n] = wr.y; g_WR[2][m][n] = wr.z; g_WR[3][m][n] = wr.w;
        float4 wl = ((const float4*)w_left)[(size_t)m * NIN + n];
        g_WL[0][m][n] = wl.x; g_WL[1][m][n] = wl.y; g_WL[2][m][n] = wl.z; g_WL[3][m][n] = wl.w;
        const float4* wp = (const float4*)(weight + (size_t)(m * NIN + n) * 20);
        #pragma unroll
        for (int q = 0; q < 5; q++) {
            float4 w4 = wp[q];
            g_WT[q*4+0][m][n] = w4.x; g_WT[q*4+1][m][n] = w4.y;
            g_WT[q*4+2][m][n] = w4.z; g_WT[q*4+3][m][n] = w4.w;
        }
    }
}

// ---------------- tiled GEMM: C[b,m] (+)= sum_n A[b,n]*B[m,n] ----------------
#define BB 128
#define BM 64
#define BK 16

// K1: xr planes.  grid = (NOUT/BM, BATCH/BB, 8)
__global__ __launch_bounds__(256) void k1_gemm() {
    __shared__ float As[BK][BB];
    __shared__ float Bs[BK][BM];

    int z  = blockIdx.z;
    int m0 = blockIdx.x * BM;
    int b0 = blockIdx.y * BB;
    int tid = threadIdx.x;
    int tx = tid & 15, ty = tid >> 4;

    const float* __restrict__ Ap = &g_XP[z][0][0] + (size_t)b0 * NIN;
    const float* __restrict__ Bp = &g_WR[c_grade[z]][0][0] + (size_t)m0 * NIN;

    int ar = tid >> 1, aq = tid & 1;     // A: 2 float4 per thread
    int br = tid >> 2, bq = tid & 3;     // B: 1 float4 per thread

    float acc[8][4];
    #pragma unroll
    for (int r = 0; r < 8; r++)
        #pragma unroll
        for (int c = 0; c < 4; c++) acc[r][c] = 0.f;

    for (int kt = 0; kt < NIN; kt += BK) {
        float4 a0 = *(const float4*)(Ap + (size_t)ar * NIN + kt + aq * 4);
        float4 a1 = *(const float4*)(Ap + (size_t)ar * NIN + kt + (aq + 2) * 4);
        float4 b4 = *(const float4*)(Bp + (size_t)br * NIN + kt + bq * 4);
        __syncthreads();
        As[aq*4+0][ar] = a0.x; As[aq*4+1][ar] = a0.y; As[aq*4+2][ar] = a0.z; As[aq*4+3][ar] = a0.w;
        As[(aq+2)*4+0][ar] = a1.x; As[(aq+2)*4+1][ar] = a1.y; As[(aq+2)*4+2][ar] = a1.z; As[(aq+2)*4+3][ar] = a1.w;
        Bs[bq*4+0][br] = b4.x; Bs[bq*4+1][br] = b4.y; Bs[bq*4+2][br] = b4.z; Bs[bq*4+3][br] = b4.w;
        __syncthreads();
        #pragma unroll
        for (int k = 0; k < BK; k++) {
            float4 fa0 = *(const float4*)&As[k][ty*8];
            float4 fa1 = *(const float4*)&As[k][ty*8+4];
            float4 fb  = *(const float4*)&Bs[k][tx*4];
            float av[8] = {fa0.x,fa0.y,fa0.z,fa0.w,fa1.x,fa1.y,fa1.z,fa1.w};
            float bv[4] = {fb.x,fb.y,fb.z,fb.w};
            #pragma unroll
            for (int r = 0; r < 8; r++)
                #pragma unroll
                for (int c = 0; c < 4; c++) acc[r][c] = fmaf(av[r], bv[c], acc[r][c]);
        }
    }

    #pragma unroll
    for (int r = 0; r < 8; r++) {
        float4 o = make_float4(acc[r][0], acc[r][1], acc[r][2], acc[r][3]);
        *(float4*)&g_XR[z][b0 + ty*8 + r][m0 + tx*4] = o;
    }
}

// ---------------- K2: grade-norm gating + 44 pair channels ----------------
__global__ void k2_pair(const float* __restrict__ norm_a) {
    int idx = blockIdx.x * blockDim.x + threadIdx.x;
    int b = idx >> 9, n = idx & 511;

    float xv[8], yv[8];
    #pragma unroll
    for (int i = 0; i < 8; i++) { xv[i] = g_XP[i][b][n]; yv[i] = g_XR[i][b][n]; }

    float4 na = *(const float4*)(norm_a + n * 4);

    float n0 = sqrtf(yv[0]*yv[0]);
    float n1 = sqrtf(yv[1]*yv[1] + yv[2]*yv[2] + yv[3]*yv[3]);
    float n2 = sqrtf(yv[4]*yv[4] + yv[5]*yv[5] + yv[6]*yv[6]);
    float n3 = sqrtf(yv[7]*yv[7]);

    float s0 = 1.f / (1.f + expf(-na.x));
    float s1 = 1.f / (1.f + expf(-na.y));
    float s2 = 1.f / (1.f + expf(-na.z));
    float s3 = 1.f / (1.f + expf(-na.w));

    float i0 = 1.f / (s0 * (n0 - 1.f) + 1.f + 1e-6f);
    float i1 = 1.f / (s1 * (n1 - 1.f) + 1.f + 1e-6f);
    float i2 = 1.f / (s2 * (n2 - 1.f) + 1.f + 1e-6f);
    float i3 = 1.f / (s3 * (n3 - 1.f) + 1.f + 1e-6f);

    yv[0] *= i0;
    yv[1] *= i1; yv[2] *= i1; yv[3] *= i1;
    yv[4] *= i2; yv[5] *= i2; yv[6] *= i2;
    yv[7] *= i3;

    float z[44];
    z[0]  = xv[0]*yv[0];
    z[1]  = xv[0]*yv[1];
    z[2]  = xv[0]*yv[2];
    z[3]  = xv[0]*yv[3];
    z[4]  = xv[0]*yv[4];
    z[5]  = xv[0]*yv[5];
    z[6]  = xv[0]*yv[6];
    z[7]  = xv[0]*yv[7];
    z[8]  = xv[1]*yv[1] + xv[2]*yv[2] + xv[3]*yv[3];
    z[9]  = xv[1]*yv[0];
    z[10] = xv[2]*yv[0];
    z[11] = xv[3]*yv[0];
    z[12] = -xv[2]*yv[4] - xv[3]*yv[5];
    z[13] =  xv[1]*yv[4] - xv[3]*yv[6];
    z[14] =  xv[1]*yv[5] + xv[2]*yv[6];
    z[15] =  xv[1]*yv[2] - xv[2]*yv[1];
    z[16] =  xv[1]*yv[3] - xv[3]*yv[1];
    z[17] =  xv[2]*yv[3] - xv[3]*yv[2];
    z[18] =  xv[3]*yv[7];
    z[19] = -xv[2]*yv[7];
    z[20] =  xv[1]*yv[7];
    z[21] =  xv[1]*yv[6] - xv[2]*yv[5] + xv[3]*yv[4];
    z[22] = -(xv[4]*yv[4] + xv[5]*yv[5] + xv[6]*yv[6]);
    z[23] =  xv[4]*yv[2] + xv[5]*yv[3];
    z[24] = -xv[4]*yv[1] + xv[6]*yv[3];
    z[25] = -xv[5]*yv[1] - xv[6]*yv[2];
    z[26] = -xv[6]*yv[7];
    z[27] =  xv[5]*yv[7];
    z[28] = -xv[4]*yv[7];
    z[29] =  xv[4]*yv[0];
    z[30] =  xv[5]*yv[0];
    z[31] =  xv[6]*yv[0];
    z[32] = -xv[5]*yv[6] + xv[6]*yv[5];
    z[33] =  xv[4]*yv[6] - xv[6]*yv[4];
    z[34] = -xv[4]*yv[5] + xv[5]*yv[4];
    z[35] =  xv[4]*yv[3] - xv[5]*yv[2] + xv[6]*yv[1];
    z[36] = -xv[7]*yv[7];
    z[37] = -xv[7]*yv[6];
    z[38] =  xv[7]*yv[5];
    z[39] = -xv[7]*yv[4];
    z[40] =  xv[7]*yv[3];
    z[41] = -xv[7]*yv[2];
    z[42] =  xv[7]*yv[1];
    z[43] =  xv[7]*yv[0];

    #pragma unroll
    for (int c = 0; c < 44; c++) g_ZP[c][b][n] = z[c];
}

// ---------------- K3: fused left + bilinear multi-channel GEMM ----------------
// grid = (NOUT/BM, BATCH/BB, 8 blades)
__global__ __launch_bounds__(256) void k3_gemm(const float* __restrict__ b_left) {
    __shared__ float As[BK][BB];
    __shared__ float Bs[BK][BM];

    int j  = blockIdx.z;
    int m0 = blockIdx.x * BM;
    int b0 = blockIdx.y * BB;
    int tid = threadIdx.x;
    int tx = tid & 15, ty = tid >> 4;

    int ar = tid >> 1, aq = tid & 1;
    int br = tid >> 2, bq = tid & 3;

    float acc[8][4];
    #pragma unroll
    for (int r = 0; r < 8; r++)
        #pragma unroll
        for (int c = 0; c < 4; c++) acc[r][c] = 0.f;

    int nch = c_nch[j];
    for (int ch = 0; ch < nch; ch++) {
        const float* __restrict__ Ap = a_plane(c_aidx[j][ch]) + (size_t)b0 * NIN;
        const float* __restrict__ Bp = b_plane(c_bidx[j][ch]) + (size_t)m0 * NIN;
        for (int kt = 0; kt < NIN; kt += BK) {
            float4 a0 = *(const float4*)(Ap + (size_t)ar * NIN + kt + aq * 4);
            float4 a1 = *(const float4*)(Ap + (size_t)ar * NIN + kt + (aq + 2) * 4);
            float4 b4 = *(const float4*)(Bp + (size_t)br * NIN + kt + bq * 4);
            __syncthreads();
            As[aq*4+0][ar] = a0.x; As[aq*4+1][ar] = a0.y; As[aq*4+2][ar] = a0.z; As[aq*4+3][ar] = a0.w;
            As[(aq+2)*4+0][ar] = a1.x; As[(aq+2)*4+1][ar] = a1.y; As[(aq+2)*4+2][ar] = a1.z; As[(aq+2)*4+3][ar] = a1.w;
            Bs[bq*4+0][br] = b4.x; Bs[bq*4+1][br] = b4.y; Bs[bq*4+2][br] = b4.z; Bs[bq*4+3][br] = b4.w;
            __syncthreads();
            #pragma unroll
            for (int k = 0; k < BK; k++) {
                float4 fa0 = *(const float4*)&As[k][ty*8];
                float4 fa1 = *(const float4*)&As[k][ty*8+4];
                float4 fb  = *(const float4*)&Bs[k][tx*4];
                float av[8] = {fa0.x,fa0.y,fa0.z,fa0.w,fa1.x,fa1.y,fa1.z,fa1.w};
                float bv[4] = {fb.x,fb.y,fb.z,fb.w};
                #pragma unroll
                for (int r = 0; r < 8; r++)
                    #pragma unroll
                    for (int c = 0; c < 4; c++) acc[r][c] = fmaf(av[r], bv[c], acc[r][c]);
            }
        }
    }

    const float RS2 = 0.70710678118654752440f;
    float bl[4] = {0.f, 0.f, 0.f, 0.f};
    if (j == 0) {
        #pragma unroll
        for (int c = 0; c < 4; c++) bl[c] = b_left[m0 + tx*4 + c];
    }
    #pragma unroll
    for (int r = 0; r < 8; r++) {
        float4 o = make_float4((acc[r][0] + bl[0]) * RS2,
                               (acc[r][1] + bl[1]) * RS2,
                               (acc[r][2] + bl[2]) * RS2,
                               (acc[r][3] + bl[3]) * RS2);
        *(float4*)&g_OUTP[j][b0 + ty*8 + r][m0 + tx*4] = o;
    }
}

// ---------------- K4: planar -> interleaved output ----------------
__global__ void k4_out(float* __restrict__ out) {
    int idx = blockIdx.x * blockDim.x + threadIdx.x;
    int b = idx >> 9, m = idx & 511;
    float4 o0 = make_float4(g_OUTP[0][b][m], g_OUTP[1][b][m], g_OUTP[2][b][m], g_OUTP[3][b][m]);
    float4 o1 = make_float4(g_OUTP[4][b][m], g_OUTP[5][b][m], g_OUTP[6][b][m], g_OUTP[7][b][m]);
    ((float4*)out)[(size_t)idx * 2 + 0] = o0;
    ((float4*)out)[(size_t)idx * 2 + 1] = o1;
}

// ---------------- launch ----------------
extern "C" void kernel_launch(void* const* d_in, const int* in_sizes, int n_in,
                              void* d_out, int out_size) {
    const float* x       = (const float*)d_in[0];
    const float* weight  = (const float*)d_in[1];
    const float* w_right = (const float*)d_in[2];
    const float* w_left  = (const float*)d_in[3];
    const float* b_left  = (const float*)d_in[4];
    const float* norm_a  = (const float*)d_in[5];
    float* out = (float*)d_out;

    int elem_threads = BATCH * NIN;           // 1M
    int eb = elem_threads / 256;

    k0_prep<<<eb, 256>>>(x, weight, w_right, w_left);

    dim3 gg(NOUT / BM, BATCH / BB, 8);
    k1_gemm<<<gg, 256>>>();
    k2_pair<<<eb, 256>>>(norm_a);
    k3_gemm<<<gg, 256>>>(b_left);
    k4_out<<<eb, 256>>>(out);
}

// round 4
// speedup vs baseline: 3.1005x; 3.1005x over previous
#include <cuda_runtime.h>
#include <cstdint>
#include <math.h>

#define BATCH 2048
#define NIN   512
#define NOUT  512
#define PLA ((size_t)BATCH * NIN)
#define PLB ((size_t)NOUT * NIN)

// ---------------- device scratch (linear planes) ----------------
__device__ float g_XP[8 * BATCH * NIN];     // x planes, tf32-rounded
__device__ float g_ZP[44 * BATCH * NIN];    // pair channels, tf32-rounded
__device__ float g_XR[8 * BATCH * NIN];     // xr (phase-1 out, fp32)
__device__ float g_OUTP[8 * BATCH * NOUT];  // planar output
__device__ float g_WR[4 * NIN * NIN];       // w_right, tf32-rounded
__device__ float g_WL[4 * NOUT * NIN];      // w_left, tf32-rounded
__device__ float g_WT[20 * NOUT * NIN];     // weight paths, tf32-rounded

__constant__ int c_grade[8] = {0,1,1,1,2,2,2,3};
__constant__ int c_nch[8] = {5,7,7,7,7,7,7,5};
__constant__ int c_aidx[8][7] = {
    {0, 8,16,30,44, 0, 0},
    {1, 9,17,20,31,34,45},
    {2,10,18,21,32,35,46},
    {3,11,19,22,33,36,47},
    {4,12,23,26,37,40,48},
    {5,13,24,27,38,41,49},
    {6,14,25,28,39,42,50},
    {7,15,29,43,51, 0, 0}
};
__constant__ int c_bidx[8][7] = {
    {0, 4, 8,14,20, 0, 0},
    {1, 5, 9,10,15,16,21},
    {1, 5, 9,10,15,16,21},
    {1, 5, 9,10,15,16,21},
    {2, 6,11,12,17,18,22},
    {2, 6,11,12,17,18,22},
    {2, 6,11,12,17,18,22},
    {3, 7,13,19,23, 0, 0}
};

// ---------------- helpers ----------------
__device__ __forceinline__ float rtf(float x) {    // round-to-nearest tf32
    uint32_t u;
    asm("cvt.rna.tf32.f32 %0, %1;" : "=r"(u) : "f"(x));
    return __uint_as_float(u);
}
__device__ __forceinline__ uint32_t smem_u32(const void* p) {
    uint32_t a;
    asm("{ .reg .u64 t; cvta.to.shared.u64 t, %1; cvt.u32.u64 %0, t; }" : "=r"(a) : "l"(p));
    return a;
}
__device__ __forceinline__ void cp16(uint32_t dst, const float* src) {
    asm volatile("cp.async.cg.shared.global [%0], [%1], 16;" :: "r"(dst), "l"(src) : "memory");
}
__device__ __forceinline__ void mma_tf32(float* c, const uint32_t* a, const uint32_t* b) {
    asm volatile(
        "mma.sync.aligned.m16n8k8.row.col.f32.tf32.tf32.f32 "
        "{%0,%1,%2,%3}, {%4,%5,%6,%7}, {%8,%9}, {%0,%1,%2,%3};"
        : "+f"(c[0]), "+f"(c[1]), "+f"(c[2]), "+f"(c[3])
        : "r"(a[0]), "r"(a[1]), "r"(a[2]), "r"(a[3]), "r"(b[0]), "r"(b[1]));
}

// ---------------- K0: transpose + tf32-round inputs into planes ----------------
__global__ void k0_prep(const float* __restrict__ x,
                        const float* __restrict__ weight,
                        const float* __restrict__ w_right,
                        const float* __restrict__ w_left) {
    int idx = blockIdx.x * blockDim.x + threadIdx.x;   // BATCH*NIN threads
    int b = idx >> 9;
    int n = idx & 511;

    float4 v0 = ((const float4*)x)[(size_t)idx * 2 + 0];
    float4 v1 = ((const float4*)x)[(size_t)idx * 2 + 1];
    size_t o = (size_t)b * NIN + n;
    g_XP[0*PLA + o] = rtf(v0.x); g_XP[1*PLA + o] = rtf(v0.y);
    g_XP[2*PLA + o] = rtf(v0.z); g_XP[3*PLA + o] = rtf(v0.w);
    g_XP[4*PLA + o] = rtf(v1.x); g_XP[5*PLA + o] = rtf(v1.y);
    g_XP[6*PLA + o] = rtf(v1.z); g_XP[7*PLA + o] = rtf(v1.w);

    if (b < NOUT) {
        int m = b;
        size_t wo = (size_t)m * NIN + n;
        float4 wr = ((const float4*)w_right)[wo];
        g_WR[0*PLB + wo] = rtf(wr.x); g_WR[1*PLB + wo] = rtf(wr.y);
        g_WR[2*PLB + wo] = rtf(wr.z); g_WR[3*PLB + wo] = rtf(wr.w);
        float4 wl = ((const float4*)w_left)[wo];
        g_WL[0*PLB + wo] = rtf(wl.x); g_WL[1*PLB + wo] = rtf(wl.y);
        g_WL[2*PLB + wo] = rtf(wl.z); g_WL[3*PLB + wo] = rtf(wl.w);
        const float4* wp = (const float4*)(weight + (size_t)(m * NIN + n) * 20);
        #pragma unroll
        for (int q = 0; q < 5; q++) {
            float4 w4 = wp[q];
            g_WT[(q*4+0)*PLB + wo] = rtf(w4.x); g_WT[(q*4+1)*PLB + wo] = rtf(w4.y);
            g_WT[(q*4+2)*PLB + wo] = rtf(w4.z); g_WT[(q*4+3)*PLB + wo] = rtf(w4.w);
        }
    }
}

// ---------------- tensor-core GEMM: C[b,m] = sum_ch sum_n A_ch[b,n]*B_ch[m,n] ----------------
// grid = (4 ntiles, 16 mtiles, 8 blades), 256 threads (8 warps, 4x2), tile 128x128.
#define SA 36                      // smem row stride (floats): conflict-free frags
#define STAGE_F (2 * 128 * SA)     // floats per stage (A + B)
#define SMEM_BYTES (2 * STAGE_F * 4)

__global__ void __launch_bounds__(256, 2) gemm_mma(int mode, const float* __restrict__ b_left) {
    extern __shared__ float sm[];
    uint32_t sbase = smem_u32(sm);

    int tid = threadIdx.x;
    int z  = blockIdx.z;
    int m0 = blockIdx.y * 128;   // batch rows
    int n0 = blockIdx.x * 128;   // out cols

    int nch = (mode == 0) ? 1 : c_nch[z];
    int n_iter = nch << 4;       // nch * (512/32)

    int wid = tid >> 5, lane = tid & 31;
    int rb = (wid >> 1) * 32;    // warp batch-row base
    int cb = (wid & 1) * 64;     // warp out-col base
    int grp = lane >> 2, tg = lane & 3;

    float acc[2][8][4];
    #pragma unroll
    for (int mi = 0; mi < 2; mi++)
        #pragma unroll
        for (int ni = 0; ni < 8; ni++)
            #pragma unroll
            for (int q = 0; q < 4; q++) acc[mi][ni][q] = 0.f;

    // stage loader: 8x cp.async(16B) for A + 8x for B per thread
    auto issue = [&](int i, int stage) {
        int ch = i >> 4, kt = (i & 15) << 5;
        const float* Ag;
        const float* Bg;
        if (mode == 0) {
            Ag = g_XP + (size_t)z * PLA;
            Bg = g_WR + (size_t)c_grade[z] * PLB;
        } else {
            int ai = c_aidx[z][ch], bi = c_bidx[z][ch];
            Ag = (ai < 8) ? g_XP + (size_t)ai * PLA : g_ZP + (size_t)(ai - 8) * PLA;
            Bg = (bi < 4) ? g_WL + (size_t)bi * PLB : g_WT + (size_t)(bi - 4) * PLB;
        }
        Ag += (size_t)m0 * NIN + kt;
        Bg += (size_t)n0 * NIN + kt;
        uint32_t Asm = sbase + (uint32_t)(stage * STAGE_F) * 4;
        uint32_t Bsm = Asm + 128 * SA * 4;
        #pragma unroll
        for (int r = 0; r < 4; r++) {
            int idx = tid + (r << 8);
            int row = idx >> 3, kq = idx & 7;
            cp16(Asm + (uint32_t)(row * SA + kq * 4) * 4, Ag + (size_t)row * NIN + kq * 4);
        }
        #pragma unroll
        for (int r = 0; r < 4; r++) {
            int idx = tid + (r << 8);
            int row = idx >> 3, kq = idx & 7;
            cp16(Bsm + (uint32_t)(row * SA + kq * 4) * 4, Bg + (size_t)row * NIN + kq * 4);
        }
        asm volatile("cp.async.commit_group;" ::: "memory");
    };

    issue(0, 0);
    for (int i = 0; i < n_iter; i++) {
        int cur = i & 1;
        if (i + 1 < n_iter) {
            issue(i + 1, cur ^ 1);
            asm volatile("cp.async.wait_group 1;" ::: "memory");
        } else {
            asm volatile("cp.async.wait_group 0;" ::: "memory");
        }
        __syncthreads();

        const float* Asm = sm + cur * STAGE_F;
        const float* Bsm = Asm + 128 * SA;
        #pragma unroll
        for (int k8 = 0; k8 < 4; k8++) {
            int kb = k8 * 8;
            uint32_t a[2][4], b[8][2];
            #pragma unroll
            for (int mi = 0; mi < 2; mi++) {
                const float* ap = Asm + (rb + mi * 16 + grp) * SA + kb + tg;
                a[mi][0] = __float_as_uint(ap[0]);
                a[mi][1] = __float_as_uint(ap[8 * SA]);
                a[mi][2] = __float_as_uint(ap[4]);
                a[mi][3] = __float_as_uint(ap[8 * SA + 4]);
            }
            #pragma unroll
            for (int ni = 0; ni < 8; ni++) {
                const float* bp = Bsm + (cb + ni * 8 + grp) * SA + kb + tg;
                b[ni][0] = __float_as_uint(bp[0]);
                b[ni][1] = __float_as_uint(bp[4]);
            }
            #pragma unroll
            for (int mi = 0; mi < 2; mi++)
                #pragma unroll
                for (int ni = 0; ni < 8; ni++)
                    mma_tf32(acc[mi][ni], a[mi], b[ni]);
        }
        __syncthreads();
    }

    // epilogue
    const float RS2 = 0.70710678118654752440f;
    float* Out = (mode == 0) ? g_XR + (size_t)z * PLA : g_OUTP + (size_t)z * PLA;
    #pragma unroll
    for (int mi = 0; mi < 2; mi++) {
        #pragma unroll
        for (int h = 0; h < 2; h++) {
            int row = m0 + rb + mi * 16 + grp + h * 8;
            float* dp = Out + (size_t)row * NOUT + n0 + cb;
            #pragma unroll
            for (int ni = 0; ni < 8; ni++) {
                int col = ni * 8 + 2 * tg;
                float v0 = acc[mi][ni][h * 2 + 0];
                float v1 = acc[mi][ni][h * 2 + 1];
                if (mode == 1) {
                    if (z == 0) {
                        v0 += b_left[n0 + cb + col];
                        v1 += b_left[n0 + cb + col + 1];
                    }
                    v0 *= RS2; v1 *= RS2;
                }
                float2 o = make_float2(v0, v1);
                *(float2*)(dp + col) = o;
            }
        }
    }
}

// ---------------- K2: gating + 44 pair channels (tf32-rounded out) ----------------
__global__ void k2_pair(const float* __restrict__ norm_a) {
    int idx = blockIdx.x * blockDim.x + threadIdx.x;
    size_t o = (size_t)idx;   // (b*512+n)

    float xv[8], yv[8];
    #pragma unroll
    for (int i = 0; i < 8; i++) { xv[i] = g_XP[i * PLA + o]; yv[i] = g_XR[i * PLA + o]; }

    int n = idx & 511;
    float4 na = *(const float4*)(norm_a + n * 4);

    float n0 = fabsf(yv[0]);
    float n1 = sqrtf(yv[1]*yv[1] + yv[2]*yv[2] + yv[3]*yv[3]);
    float n2 = sqrtf(yv[4]*yv[4] + yv[5]*yv[5] + yv[6]*yv[6]);
    float n3 = fabsf(yv[7]);

    float s0 = 1.f / (1.f + expf(-na.x));
    float s1 = 1.f / (1.f + expf(-na.y));
    float s2 = 1.f / (1.f + expf(-na.z));
    float s3 = 1.f / (1.f + expf(-na.w));

    float i0 = 1.f / (s0 * (n0 - 1.f) + 1.f + 1e-6f);
    float i1 = 1.f / (s1 * (n1 - 1.f) + 1.f + 1e-6f);
    float i2 = 1.f / (s2 * (n2 - 1.f) + 1.f + 1e-6f);
    float i3 = 1.f / (s3 * (n3 - 1.f) + 1.f + 1e-6f);

    yv[0] *= i0;
    yv[1] *= i1; yv[2] *= i1; yv[3] *= i1;
    yv[4] *= i2; yv[5] *= i2; yv[6] *= i2;
    yv[7] *= i3;

    float zc[44];
    zc[0]  = xv[0]*yv[0];
    zc[1]  = xv[0]*yv[1];
    zc[2]  = xv[0]*yv[2];
    zc[3]  = xv[0]*yv[3];
    zc[4]  = xv[0]*yv[4];
    zc[5]  = xv[0]*yv[5];
    zc[6]  = xv[0]*yv[6];
    zc[7]  = xv[0]*yv[7];
    zc[8]  = xv[1]*yv[1] + xv[2]*yv[2] + xv[3]*yv[3];
    zc[9]  = xv[1]*yv[0];
    zc[10] = xv[2]*yv[0];
    zc[11] = xv[3]*yv[0];
    zc[12] = -xv[2]*yv[4] - xv[3]*yv[5];
    zc[13] =  xv[1]*yv[4] - xv[3]*yv[6];
    zc[14] =  xv[1]*yv[5] + xv[2]*yv[6];
    zc[15] =  xv[1]*yv[2] - xv[2]*yv[1];
    zc[16] =  xv[1]*yv[3] - xv[3]*yv[1];
    zc[17] =  xv[2]*yv[3] - xv[3]*yv[2];
    zc[18] =  xv[3]*yv[7];
    zc[19] = -xv[2]*yv[7];
    zc[20] =  xv[1]*yv[7];
    zc[21] =  xv[1]*yv[6] - xv[2]*yv[5] + xv[3]*yv[4];
    zc[22] = -(xv[4]*yv[4] + xv[5]*yv[5] + xv[6]*yv[6]);
    zc[23] =  xv[4]*yv[2] + xv[5]*yv[3];
    zc[24] = -xv[4]*yv[1] + xv[6]*yv[3];
    zc[25] = -xv[5]*yv[1] - xv[6]*yv[2];
    zc[26] = -xv[6]*yv[7];
    zc[27] =  xv[5]*yv[7];
    zc[28] = -xv[4]*yv[7];
    zc[29] =  xv[4]*yv[0];
    zc[30] =  xv[5]*yv[0];
    zc[31] =  xv[6]*yv[0];
    zc[32] = -xv[5]*yv[6] + xv[6]*yv[5];
    zc[33] =  xv[4]*yv[6] - xv[6]*yv[4];
    zc[34] = -xv[4]*yv[5] + xv[5]*yv[4];
    zc[35] =  xv[4]*yv[3] - xv[5]*yv[2] + xv[6]*yv[1];
    zc[36] = -xv[7]*yv[7];
    zc[37] = -xv[7]*yv[6];
    zc[38] =  xv[7]*yv[5];
    zc[39] = -xv[7]*yv[4];
    zc[40] =  xv[7]*yv[3];
    zc[41] = -xv[7]*yv[2];
    zc[42] =  xv[7]*yv[1];
    zc[43] =  xv[7]*yv[0];

    #pragma unroll
    for (int c = 0; c < 44; c++) g_ZP[c * PLA + o] = rtf(zc[c]);
}

// ---------------- K4: planar -> interleaved output ----------------
__global__ void k4_out(float* __restrict__ out) {
    int idx = blockIdx.x * blockDim.x + threadIdx.x;   // over BATCH*NOUT
    size_t o = (size_t)idx;
    float4 o0, o1;
    o0.x = g_OUTP[0*PLA + o]; o0.y = g_OUTP[1*PLA + o];
    o0.z = g_OUTP[2*PLA + o]; o0.w = g_OUTP[3*PLA + o];
    o1.x = g_OUTP[4*PLA + o]; o1.y = g_OUTP[5*PLA + o];
    o1.z = g_OUTP[6*PLA + o]; o1.w = g_OUTP[7*PLA + o];
    ((float4*)out)[o * 2 + 0] = o0;
    ((float4*)out)[o * 2 + 1] = o1;
}

// ---------------- launch ----------------
extern "C" void kernel_launch(void* const* d_in, const int* in_sizes, int n_in,
                              void* d_out, int out_size) {
    const float* x       = (const float*)d_in[0];
    const float* weight  = (const float*)d_in[1];
    const float* w_right = (const float*)d_in[2];
    const float* w_left  = (const float*)d_in[3];
    const float* b_left  = (const float*)d_in[4];
    const float* norm_a  = (const float*)d_in[5];
    float* out = (float*)d_out;

    cudaFuncSetAttribute(gemm_mma, cudaFuncAttributeMaxDynamicSharedMemorySize, SMEM_BYTES);

    int eb = (BATCH * NIN) / 256;   // 4096 blocks
    k0_prep<<<eb, 256>>>(x, weight, w_right, w_left);

    dim3 gg(NOUT / 128, BATCH / 128, 8);
    gemm_mma<<<gg, 256, SMEM_BYTES>>>(0, nullptr);
    k2_pair<<<eb, 256>>>(norm_a);
    gemm_mma<<<gg, 256, SMEM_BYTES>>>(1, b_left);
    k4_out<<<(BATCH * NOUT) / 256, 256>>>(out);
}

// round 5
// speedup vs baseline: 3.2881x; 1.0605x over previous
#include <cuda_runtime.h>
#include <cstdint>
#include <math.h>

#define BATCH 2048
#define NIN   512
#define NOUT  512
#define PLA ((size_t)BATCH * NIN)
#define PLB ((size_t)NOUT * NIN)

// ---------------- device scratch ----------------
// GEMM operand planes in "atom" layout:
//  plane = tiles of 128 rows x 32 k (4096 floats, 16KB), tile idx = (k>>5)*nR + (row>>7)
//  tile  = atoms of 8 rows x 16 k (128 floats), atom idx = ((row&127)>>3)*2 + ((k&31)>>4)
//  atom  = float off ((row&7)*4 + (k&3))*4 + ((k>>2)&3)
//  => thread (grp,tg) of a warp loads its m16n8k8 fragment for 2 k8 steps as ONE float4.
__device__ float g_XP[8 * BATCH * NIN];     // x planes (atom, nR=16), tf32
__device__ float g_ZP[44 * BATCH * NIN];    // pair channels (atom, nR=16), tf32
__device__ float g_XR[8 * BATCH * NIN];     // xr (atom, nR=16), fp32
__device__ float g_OUTP[8 * BATCH * NOUT];  // planar LINEAR output
__device__ float g_WR[4 * NIN * NIN];       // w_right (atom, nR=4), tf32
__device__ float g_WL[4 * NOUT * NIN];      // w_left (atom, nR=4), tf32
__device__ float g_WT[20 * NOUT * NIN];     // weight paths (atom, nR=4), tf32

__constant__ int c_grade[8] = {0,1,1,1,2,2,2,3};
__constant__ int c_nch[8] = {5,7,7,7,7,7,7,5};
__constant__ int c_aidx[8][7] = {
    {0, 8,16,30,44, 0, 0},
    {1, 9,17,20,31,34,45},
    {2,10,18,21,32,35,46},
    {3,11,19,22,33,36,47},
    {4,12,23,26,37,40,48},
    {5,13,24,27,38,41,49},
    {6,14,25,28,39,42,50},
    {7,15,29,43,51, 0, 0}
};
__constant__ int c_bidx[8][7] = {
    {0, 4, 8,14,20, 0, 0},
    {1, 5, 9,10,15,16,21},
    {1, 5, 9,10,15,16,21},
    {1, 5, 9,10,15,16,21},
    {2, 6,11,12,17,18,22},
    {2, 6,11,12,17,18,22},
    {2, 6,11,12,17,18,22},
    {3, 7,13,19,23, 0, 0}
};

// ---------------- helpers ----------------
__device__ __forceinline__ float rtf(float x) {
    uint32_t u;
    asm("cvt.rna.tf32.f32 %0, %1;" : "=r"(u) : "f"(x));
    return __uint_as_float(u);
}
__device__ __forceinline__ uint32_t smem_u32(const void* p) {
    uint32_t a;
    asm("{ .reg .u64 t; cvta.to.shared.u64 t, %1; cvt.u32.u64 %0, t; }" : "=r"(a) : "l"(p));
    return a;
}
__device__ __forceinline__ void cp16(uint32_t dst, const float* src) {
    asm volatile("cp.async.cg.shared.global [%0], [%1], 16;" :: "r"(dst), "l"(src) : "memory");
}
__device__ __forceinline__ void mma_tf32(float* c, uint32_t a0, uint32_t a1, uint32_t a2, uint32_t a3,
                                         uint32_t b0, uint32_t b1) {
    asm volatile(
        "mma.sync.aligned.m16n8k8.row.col.f32.tf32.tf32.f32 "
        "{%0,%1,%2,%3}, {%4,%5,%6,%7}, {%8,%9}, {%0,%1,%2,%3};"
        : "+f"(c[0]), "+f"(c[1]), "+f"(c[2]), "+f"(c[3])
        : "r"(a0), "r"(a1), "r"(a2), "r"(a3), "r"(b0), "r"(b1));
}

// quad-write base: row r, k-group `group` (16-k groups), X = k&3 (t=ac>>2 spans the float4)
__device__ __forceinline__ size_t qbase(int r, int group, int X, int nR) {
    return ((size_t)((group >> 1) * nR + (r >> 7))) * 4096
         + (size_t)((((r & 127) >> 3) * 2 + (group & 1)) * 128 + ((r & 7) * 4 + X) * 4);
}
// full scalar offset for (row r, k c)
__device__ __forceinline__ size_t atomOff(int r, int c, int nR) {
    return ((size_t)((c >> 5) * nR + (r >> 7))) * 4096
         + (size_t)(((((r & 127) >> 3) * 2 + ((c & 31) >> 4)) * 128)
                    + ((r & 7) * 4 + (c & 3)) * 4 + ((c >> 2) & 3));
}

// ---------------- K0: transpose + tf32-round inputs into atom planes ----------------
__global__ void k0_prep(const float* __restrict__ x,
                        const float* __restrict__ weight,
                        const float* __restrict__ w_right,
                        const float* __restrict__ w_left) {
    int idx = blockIdx.x * blockDim.x + threadIdx.x;   // BATCH*128
    int b = idx >> 7;
    int j = idx & 127;
    int group = j >> 2, X = j & 3;
    int k0v = group * 16 + X;                          // k values: k0v + 4t

    float xb[8][4];
    #pragma unroll
    for (int t = 0; t < 4; t++) {
        int k = k0v + 4 * t;
        const float4* p = (const float4*)(x + ((size_t)b * 512 + k) * 8);
        float4 f0 = p[0], f1 = p[1];
        xb[0][t] = f0.x; xb[1][t] = f0.y; xb[2][t] = f0.z; xb[3][t] = f0.w;
        xb[4][t] = f1.x; xb[5][t] = f1.y; xb[6][t] = f1.z; xb[7][t] = f1.w;
    }
    size_t xo = qbase(b, group, X, 16);
    #pragma unroll
    for (int bl = 0; bl < 8; bl++) {
        float4 o = make_float4(rtf(xb[bl][0]), rtf(xb[bl][1]), rtf(xb[bl][2]), rtf(xb[bl][3]));
        *(float4*)(g_XP + (size_t)bl * PLA + xo) = o;
    }

    if (b < NOUT) {
        int m = b;
        size_t wo = qbase(m, group, X, 4);
        float wr[4][4], wl[4][4], wt[20][4];
        #pragma unroll
        for (int t = 0; t < 4; t++) {
            int k = k0v + 4 * t;
            float4 r = ((const float4*)w_right)[(size_t)m * 512 + k];
            wr[0][t] = r.x; wr[1][t] = r.y; wr[2][t] = r.z; wr[3][t] = r.w;
            float4 l = ((const float4*)w_left)[(size_t)m * 512 + k];
            wl[0][t] = l.x; wl[1][t] = l.y; wl[2][t] = l.z; wl[3][t] = l.w;
            const float4* wp = (const float4*)(weight + ((size_t)m * 512 + k) * 20);
            #pragma unroll
            for (int q = 0; q < 5; q++) {
                float4 f = wp[q];
                wt[q*4+0][t] = f.x; wt[q*4+1][t] = f.y; wt[q*4+2][t] = f.z; wt[q*4+3][t] = f.w;
            }
        }
        #pragma unroll
        for (int g = 0; g < 4; g++) {
            float4 o = make_float4(rtf(wr[g][0]), rtf(wr[g][1]), rtf(wr[g][2]), rtf(wr[g][3]));
            *(float4*)(g_WR + (size_t)g * PLB + wo) = o;
            float4 p = make_float4(rtf(wl[g][0]), rtf(wl[g][1]), rtf(wl[g][2]), rtf(wl[g][3]));
            *(float4*)(g_WL + (size_t)g * PLB + wo) = p;
        }
        #pragma unroll
        for (int q = 0; q < 20; q++) {
            float4 o = make_float4(rtf(wt[q][0]), rtf(wt[q][1]), rtf(wt[q][2]), rtf(wt[q][3]));
            *(float4*)(g_WT + (size_t)q * PLB + wo) = o;
        }
    }
}

// ---------------- tensor-core GEMM, atom layout, 3-stage cp.async ----------------
// grid = (4 ntiles, 16 mtiles, 8 blades), 256 threads (8 warps 4x2), CTA tile 128x128.
#define STAGE_F 8192                     // A 4096 + B 4096 floats per stage
#define SMEM_BYTES (3 * STAGE_F * 4)     // 98304

__global__ void __launch_bounds__(256, 2) gemm_mma(int mode, const float* __restrict__ b_left) {
    extern __shared__ float sm[];
    uint32_t sbase = smem_u32(sm);

    int tid = threadIdx.x;
    int z  = blockIdx.z;
    int mt = blockIdx.y;          // batch row tile
    int nt = blockIdx.x;          // out col tile
    int m0 = mt * 128, n0 = nt * 128;

    int nch = (mode == 0) ? 1 : c_nch[z];
    int n_iter = nch << 4;

    int wid = tid >> 5, lane = tid & 31;
    int rb = (wid >> 1) * 32;     // warp row base within tile
    int cb = (wid & 1) * 64;      // warp col base within tile
    int grp = lane >> 2, tg = lane & 3;

    float acc[2][8][4];
    #pragma unroll
    for (int mi = 0; mi < 2; mi++)
        #pragma unroll
        for (int ni = 0; ni < 8; ni++)
            #pragma unroll
            for (int q = 0; q < 4; q++) acc[mi][ni][q] = 0.f;

    auto issue = [&](int i, int slot) {
        int ch = i >> 4, q = i & 15;
        const float* Ag;
        const float* Bg;
        if (mode == 0) {
            Ag = g_XP + (size_t)z * PLA;
            Bg = g_WR + (size_t)c_grade[z] * PLB;
        } else {
            int ai = c_aidx[z][ch], bi = c_bidx[z][ch];
            Ag = (ai < 8) ? g_XP + (size_t)ai * PLA : g_ZP + (size_t)(ai - 8) * PLA;
            Bg = (bi < 4) ? g_WL + (size_t)bi * PLB : g_WT + (size_t)(bi - 4) * PLB;
        }
        Ag += (size_t)(q * 16 + mt) * 4096;     // A tile (contiguous 16KB)
        Bg += (size_t)(q * 4 + nt) * 4096;      // B tile
        uint32_t Asm = sbase + (uint32_t)(slot * STAGE_F) * 4;
        uint32_t Bsm = Asm + 4096 * 4;
        #pragma unroll
        for (int r = 0; r < 4; r++) {
            int e = tid + (r << 8);             // 16B chunk index 0..1023
            cp16(Asm + (uint32_t)e * 16, Ag + e * 4);
        }
        #pragma unroll
        for (int r = 0; r < 4; r++) {
            int e = tid + (r << 8);
            cp16(Bsm + (uint32_t)e * 16, Bg + e * 4);
        }
        asm volatile("cp.async.commit_group;" ::: "memory");
    };

    issue(0, 0);
    issue(1, 1);

    int artA = (rb >> 3);         // 4*(wid>>1)
    int artB = (cb >> 3) + grp;   // base atom row of B frags uses +ni

    for (int i = 0; i < n_iter; i++) {
        if (i + 1 < n_iter) {
            asm volatile("cp.async.wait_group 1;" ::: "memory");
        } else {
            asm volatile("cp.async.wait_group 0;" ::: "memory");
        }
        __syncthreads();
        if (i + 2 < n_iter) issue(i + 2, (i + 2) % 3);

        const float* At = sm + (i % 3) * STAGE_F;
        const float* Bt = At + 4096;
        int fl = grp * 16 + tg * 4;   // lane offset within atom

        #pragma unroll
        for (int kc = 0; kc < 2; kc++) {
            float4 fa[2][2];
            #pragma unroll
            for (int mi = 0; mi < 2; mi++) {
                int ar0 = artA + mi * 2;
                fa[mi][0] = *(const float4*)(At + (ar0 * 2 + kc) * 128 + fl);
                fa[mi][1] = *(const float4*)(At + ((ar0 + 1) * 2 + kc) * 128 + fl);
            }
            float4 fb[8];
            #pragma unroll
            for (int ni = 0; ni < 8; ni++) {
                int br0 = (cb >> 3) + ni;
                // B atom row includes +grp via fl's grp*16? No: fl row part is grp (B "row" = out col)
                fb[ni] = *(const float4*)(Bt + (br0 * 2 + kc) * 128 + fl);
            }
            #pragma unroll
            for (int mi = 0; mi < 2; mi++)
                #pragma unroll
                for (int ni = 0; ni < 8; ni++) {
                    mma_tf32(acc[mi][ni],
                             __float_as_uint(fa[mi][0].x), __float_as_uint(fa[mi][1].x),
                             __float_as_uint(fa[mi][0].y), __float_as_uint(fa[mi][1].y),
                             __float_as_uint(fb[ni].x), __float_as_uint(fb[ni].y));
                    mma_tf32(acc[mi][ni],
                             __float_as_uint(fa[mi][0].z), __float_as_uint(fa[mi][1].z),
                             __float_as_uint(fa[mi][0].w), __float_as_uint(fa[mi][1].w),
                             __float_as_uint(fb[ni].z), __float_as_uint(fb[ni].w));
                }
        }
        __syncthreads();
    }

    // epilogue
    const float RS2 = 0.70710678118654752440f;
    if (mode == 0) {
        // write xr plane in ATOM layout (consumed by k2 as quads)
        float* XRp = g_XR + (size_t)z * PLA;
        #pragma unroll
        for (int mi = 0; mi < 2; mi++)
            #pragma unroll
            for (int h = 0; h < 2; h++) {
                int r = m0 + rb + mi * 16 + grp + h * 8;
                #pragma unroll
                for (int ni = 0; ni < 8; ni++) {
                    int c0 = n0 + cb + ni * 8 + 2 * tg;
                    XRp[atomOff(r, c0, 16)]     = acc[mi][ni][h * 2 + 0];
                    XRp[atomOff(r, c0 + 1, 16)] = acc[mi][ni][h * 2 + 1];
                }
            }
    } else {
        float* Out = g_OUTP + (size_t)z * PLA;
        #pragma unroll
        for (int mi = 0; mi < 2; mi++)
            #pragma unroll
            for (int h = 0; h < 2; h++) {
                int row = m0 + rb + mi * 16 + grp + h * 8;
                float* dp = Out + (size_t)row * NOUT + n0 + cb;
                #pragma unroll
                for (int ni = 0; ni < 8; ni++) {
                    int col = ni * 8 + 2 * tg;
                    float v0 = acc[mi][ni][h * 2 + 0];
                    float v1 = acc[mi][ni][h * 2 + 1];
                    if (z == 0) {
                        v0 += b_left[n0 + cb + col];
                        v1 += b_left[n0 + cb + col + 1];
                    }
                    *(float2*)(dp + col) = make_float2(v0 * RS2, v1 * RS2);
                }
            }
    }
}

// ---------------- K2: gating + 44 pair channels (atom quads in/out) ----------------
__global__ void k2_pair(const float* __restrict__ norm_a) {
    int idx = blockIdx.x * blockDim.x + threadIdx.x;   // BATCH*128
    int b = idx >> 7;
    int j = idx & 127;
    int group = j >> 2, X = j & 3;
    int k0v = group * 16 + X;

    size_t qo = qbase(b, group, X, 16);
    float xv[8][4], yv[8][4];
    #pragma unroll
    for (int bl = 0; bl < 8; bl++) {
        float4 fx = *(const float4*)(g_XP + (size_t)bl * PLA + qo);
        xv[bl][0] = fx.x; xv[bl][1] = fx.y; xv[bl][2] = fx.z; xv[bl][3] = fx.w;
        float4 fy = *(const float4*)(g_XR + (size_t)bl * PLA + qo);
        yv[bl][0] = fy.x; yv[bl][1] = fy.y; yv[bl][2] = fy.z; yv[bl][3] = fy.w;
    }

    #pragma unroll
    for (int t = 0; t < 4; t++) {
        int n = k0v + 4 * t;
        float4 na = *(const float4*)(norm_a + n * 4);
        float n0 = fabsf(yv[0][t]);
        float n1 = sqrtf(yv[1][t]*yv[1][t] + yv[2][t]*yv[2][t] + yv[3][t]*yv[3][t]);
        float n2 = sqrtf(yv[4][t]*yv[4][t] + yv[5][t]*yv[5][t] + yv[6][t]*yv[6][t]);
        float n3 = fabsf(yv[7][t]);
        float s0 = 1.f / (1.f + expf(-na.x));
        float s1 = 1.f / (1.f + expf(-na.y));
        float s2 = 1.f / (1.f + expf(-na.z));
        float s3 = 1.f / (1.f + expf(-na.w));
        float i0 = 1.f / (s0 * (n0 - 1.f) + 1.f + 1e-6f);
        float i1 = 1.f / (s1 * (n1 - 1.f) + 1.f + 1e-6f);
        float i2 = 1.f / (s2 * (n2 - 1.f) + 1.f + 1e-6f);
        float i3 = 1.f / (s3 * (n3 - 1.f) + 1.f + 1e-6f);
        yv[0][t] *= i0;
        yv[1][t] *= i1; yv[2][t] *= i1; yv[3][t] *= i1;
        yv[4][t] *= i2; yv[5][t] *= i2; yv[6][t] *= i2;
        yv[7][t] *= i3;
    }

    auto emit = [&](int c, auto f) {
        float4 o = make_float4(rtf(f(0)), rtf(f(1)), rtf(f(2)), rtf(f(3)));
        *(float4*)(g_ZP + (size_t)c * PLA + qo) = o;
    };
    emit(0,  [&](int t){ return xv[0][t]*yv[0][t]; });
    emit(1,  [&](int t){ return xv[0][t]*yv[1][t]; });
    emit(2,  [&](int t){ return xv[0][t]*yv[2][t]; });
    emit(3,  [&](int t){ return xv[0][t]*yv[3][t]; });
    emit(4,  [&](int t){ return xv[0][t]*yv[4][t]; });
    emit(5,  [&](int t){ return xv[0][t]*yv[5][t]; });
    emit(6,  [&](int t){ return xv[0][t]*yv[6][t]; });
    emit(7,  [&](int t){ return xv[0][t]*yv[7][t]; });
    emit(8,  [&](int t){ return xv[1][t]*yv[1][t] + xv[2][t]*yv[2][t] + xv[3][t]*yv[3][t]; });
    emit(9,  [&](int t){ return xv[1][t]*yv[0][t]; });
    emit(10, [&](int t){ return xv[2][t]*yv[0][t]; });
    emit(11, [&](int t){ return xv[3][t]*yv[0][t]; });
    emit(12, [&](int t){ return -xv[2][t]*yv[4][t] - xv[3][t]*yv[5][t]; });
    emit(13, [&](int t){ return  xv[1][t]*yv[4][t] - xv[3][t]*yv[6][t]; });
    emit(14, [&](int t){ return  xv[1][t]*yv[5][t] + xv[2][t]*yv[6][t]; });
    emit(15, [&](int t){ return  xv[1][t]*yv[2][t] - xv[2][t]*yv[1][t]; });
    emit(16, [&](int t){ return  xv[1][t]*yv[3][t] - xv[3][t]*yv[1][t]; });
    emit(17, [&](int t){ return  xv[2][t]*yv[3][t] - xv[3][t]*yv[2][t]; });
    emit(18, [&](int t){ return  xv[3][t]*yv[7][t]; });
    emit(19, [&](int t){ return -xv[2][t]*yv[7][t]; });
    emit(20, [&](int t){ return  xv[1][t]*yv[7][t]; });
    emit(21, [&](int t){ return  xv[1][t]*yv[6][t] - xv[2][t]*yv[5][t] + xv[3][t]*yv[4][t]; });
    emit(22, [&](int t){ return -(xv[4][t]*yv[4][t] + xv[5][t]*yv[5][t] + xv[6][t]*yv[6][t]); });
    emit(23, [&](int t){ return  xv[4][t]*yv[2][t] + xv[5][t]*yv[3][t]; });
    emit(24, [&](int t){ return -xv[4][t]*yv[1][t] + xv[6][t]*yv[3][t]; });
    emit(25, [&](int t){ return -xv[5][t]*yv[1][t] - xv[6][t]*yv[2][t]; });
    emit(26, [&](int t){ return -xv[6][t]*yv[7][t]; });
    emit(27, [&](int t){ return  xv[5][t]*yv[7][t]; });
    emit(28, [&](int t){ return -xv[4][t]*yv[7][t]; });
    emit(29, [&](int t){ return  xv[4][t]*yv[0][t]; });
    emit(30, [&](int t){ return  xv[5][t]*yv[0][t]; });
    emit(31, [&](int t){ return  xv[6][t]*yv[0][t]; });
    emit(32, [&](int t){ return -xv[5][t]*yv[6][t] + xv[6][t]*yv[5][t]; });
    emit(33, [&](int t){ return  xv[4][t]*yv[6][t] - xv[6][t]*yv[4][t]; });
    emit(34, [&](int t){ return -xv[4][t]*yv[5][t] + xv[5][t]*yv[4][t]; });
    emit(35, [&](int t){ return  xv[4][t]*yv[3][t] - xv[5][t]*yv[2][t] + xv[6][t]*yv[1][t]; });
    emit(36, [&](int t){ return -xv[7][t]*yv[7][t]; });
    emit(37, [&](int t){ return -xv[7][t]*yv[6][t]; });
    emit(38, [&](int t){ return  xv[7][t]*yv[5][t]; });
    emit(39, [&](int t){ return -xv[7][t]*yv[4][t]; });
    emit(40, [&](int t){ return  xv[7][t]*yv[3][t]; });
    emit(41, [&](int t){ return -xv[7][t]*yv[2][t]; });
    emit(42, [&](int t){ return  xv[7][t]*yv[1][t]; });
    emit(43, [&](int t){ return  xv[7][t]*yv[0][t]; });
}

// ---------------- K4: planar -> interleaved output ----------------
__global__ void k4_out(float* __restrict__ out) {
    int idx = blockIdx.x * blockDim.x + threadIdx.x;   // BATCH*NOUT
    size_t o = (size_t)idx;
    float4 o0, o1;
    o0.x = g_OUTP[0*PLA + o]; o0.y = g_OUTP[1*PLA + o];
    o0.z = g_OUTP[2*PLA + o]; o0.w = g_OUTP[3*PLA + o];
    o1.x = g_OUTP[4*PLA + o]; o1.y = g_OUTP[5*PLA + o];
    o1.z = g_OUTP[6*PLA + o]; o1.w = g_OUTP[7*PLA + o];
    ((float4*)out)[o * 2 + 0] = o0;
    ((float4*)out)[o * 2 + 1] = o1;
}

// ---------------- launch ----------------
extern "C" void kernel_launch(void* const* d_in, const int* in_sizes, int n_in,
                              void* d_out, int out_size) {
    const float* x       = (const float*)d_in[0];
    const float* weight  = (const float*)d_in[1];
    const float* w_right = (const float*)d_in[2];
    const float* w_left  = (const float*)d_in[3];
    const float* b_left  = (const float*)d_in[4];
    const float* norm_a  = (const float*)d_in[5];
    float* out = (float*)d_out;

    cudaFuncSetAttribute(gemm_mma, cudaFuncAttributeMaxDynamicSharedMemorySize, SMEM_BYTES);

    int eb = (BATCH * 128) / 256;   // 1024 blocks for quad-mapped elementwise kernels
    k0_prep<<<eb, 256>>>(x, weight, w_right, w_left);

    dim3 gg(NOUT / 128, BATCH / 128, 8);
    gemm_mma<<<gg, 256, SMEM_BYTES>>>(0, nullptr);
    k2_pair<<<eb, 256>>>(norm_a);
    gemm_mma<<<gg, 256, SMEM_BYTES>>>(1, b_left);
    k4_out<<<(BATCH * NOUT) / 256, 256>>>(out);
}

// round 7
// speedup vs baseline: 3.4115x; 1.0375x over previous
#include <cuda_runtime.h>
#include <cstdint>
#include <math.h>

#define BATCH 2048
#define NIN   512
#define NOUT  512
#define PLA ((size_t)BATCH * NIN)
#define PLB ((size_t)NOUT * NIN)

// ---------------- device scratch ----------------
// "Atom" plane layout:
//  plane = tiles of 128 rows x 32 k (4096 floats, 16KB), tile idx = (k>>5)*nR + (row>>7)
//  tile  = atoms of 8 rows x 16 k (128 floats), atom idx = ((row&127)>>3)*2 + ((k&31)>>4)
//  atom  = float off ((row&7)*4 + (k&3))*4 + ((k>>2)&3)
__device__ float g_XP[8 * BATCH * NIN];     // x planes (atom, nR=16), tf32
__device__ float g_ZP[44 * BATCH * NIN];    // pair channels (atom, nR=16), tf32
__device__ float g_XR[8 * BATCH * NIN];     // xr (atom, nR=16), fp32
__device__ float g_OUTP[8 * BATCH * NOUT];  // planar LINEAR output
__device__ float g_WR[4 * NIN * NIN];       // w_right (atom, nR=4), tf32
__device__ float g_WL[4 * NOUT * NIN];      // w_left (atom, nR=4), tf32
__device__ float g_WT[20 * NOUT * NIN];     // weight paths (atom, nR=4), tf32

__constant__ int c_grade[8] = {0,1,1,1,2,2,2,3};
__constant__ int c_nch[8] = {5,7,7,7,7,7,7,5};
__constant__ int c_aidx[8][7] = {
    {0, 8,16,30,44, 0, 0},
    {1, 9,17,20,31,34,45},
    {2,10,18,21,32,35,46},
    {3,11,19,22,33,36,47},
    {4,12,23,26,37,40,48},
    {5,13,24,27,38,41,49},
    {6,14,25,28,39,42,50},
    {7,15,29,43,51, 0, 0}
};
__constant__ int c_bidx[8][7] = {
    {0, 4, 8,14,20, 0, 0},
    {1, 5, 9,10,15,16,21},
    {1, 5, 9,10,15,16,21},
    {1, 5, 9,10,15,16,21},
    {2, 6,11,12,17,18,22},
    {2, 6,11,12,17,18,22},
    {2, 6,11,12,17,18,22},
    {3, 7,13,19,23, 0, 0}
};

// ---------------- helpers ----------------
__device__ __forceinline__ float rtf(float x) {
    uint32_t u;
    asm("cvt.rna.tf32.f32 %0, %1;" : "=r"(u) : "f"(x));
    return __uint_as_float(u);
}
__device__ __forceinline__ uint32_t smem_u32(const void* p) {
    uint32_t a;
    asm("{ .reg .u64 t; cvta.to.shared.u64 t, %1; cvt.u32.u64 %0, t; }" : "=r"(a) : "l"(p));
    return a;
}
__device__ __forceinline__ void cp16(uint32_t dst, const float* src) {
    asm volatile("cp.async.cg.shared.global [%0], [%1], 16;" :: "r"(dst), "l"(src) : "memory");
}
__device__ __forceinline__ void mma_tf32(float* c, uint32_t a0, uint32_t a1, uint32_t a2, uint32_t a3,
                                         uint32_t b0, uint32_t b1) {
    asm volatile(
        "mma.sync.aligned.m16n8k8.row.col.f32.tf32.tf32.f32 "
        "{%0,%1,%2,%3}, {%4,%5,%6,%7}, {%8,%9}, {%0,%1,%2,%3};"
        : "+f"(c[0]), "+f"(c[1]), "+f"(c[2]), "+f"(c[3])
        : "r"(a0), "r"(a1), "r"(a2), "r"(a3), "r"(b0), "r"(b1));
}

__device__ __forceinline__ size_t qbase(int r, int group, int X, int nR) {
    return ((size_t)((group >> 1) * nR + (r >> 7))) * 4096
         + (size_t)((((r & 127) >> 3) * 2 + (group & 1)) * 128 + ((r & 7) * 4 + X) * 4);
}

// ---------------- K0: transpose + tf32-round inputs into atom planes ----------------
__global__ void k0_prep(const float* __restrict__ x,
                        const float* __restrict__ weight,
                        const float* __restrict__ w_right,
                        const float* __restrict__ w_left) {
    int idx = blockIdx.x * blockDim.x + threadIdx.x;   // BATCH*128
    int b = idx >> 7;
    int j = idx & 127;
    int group = j >> 2, X = j & 3;
    int k0v = group * 16 + X;

    float xb[8][4];
    #pragma unroll
    for (int t = 0; t < 4; t++) {
        int k = k0v + 4 * t;
        const float4* p = (const float4*)(x + ((size_t)b * 512 + k) * 8);
        float4 f0 = p[0], f1 = p[1];
        xb[0][t] = f0.x; xb[1][t] = f0.y; xb[2][t] = f0.z; xb[3][t] = f0.w;
        xb[4][t] = f1.x; xb[5][t] = f1.y; xb[6][t] = f1.z; xb[7][t] = f1.w;
    }
    size_t xo = qbase(b, group, X, 16);
    #pragma unroll
    for (int bl = 0; bl < 8; bl++) {
        float4 o = make_float4(rtf(xb[bl][0]), rtf(xb[bl][1]), rtf(xb[bl][2]), rtf(xb[bl][3]));
        *(float4*)(g_XP + (size_t)bl * PLA + xo) = o;
    }

    if (b < NOUT) {
        int m = b;
        size_t wo = qbase(m, group, X, 4);
        float wr[4][4], wl[4][4], wt[20][4];
        #pragma unroll
        for (int t = 0; t < 4; t++) {
            int k = k0v + 4 * t;
            float4 r = ((const float4*)w_right)[(size_t)m * 512 + k];
            wr[0][t] = r.x; wr[1][t] = r.y; wr[2][t] = r.z; wr[3][t] = r.w;
            float4 l = ((const float4*)w_left)[(size_t)m * 512 + k];
            wl[0][t] = l.x; wl[1][t] = l.y; wl[2][t] = l.z; wl[3][t] = l.w;
            const float4* wp = (const float4*)(weight + ((size_t)m * 512 + k) * 20);
            #pragma unroll
            for (int q = 0; q < 5; q++) {
                float4 f = wp[q];
                wt[q*4+0][t] = f.x; wt[q*4+1][t] = f.y; wt[q*4+2][t] = f.z; wt[q*4+3][t] = f.w;
            }
        }
        #pragma unroll
        for (int g = 0; g < 4; g++) {
            float4 o = make_float4(rtf(wr[g][0]), rtf(wr[g][1]), rtf(wr[g][2]), rtf(wr[g][3]));
            *(float4*)(g_WR + (size_t)g * PLB + wo) = o;
            float4 p = make_float4(rtf(wl[g][0]), rtf(wl[g][1]), rtf(wl[g][2]), rtf(wl[g][3]));
            *(float4*)(g_WL + (size_t)g * PLB + wo) = p;
        }
        #pragma unroll
        for (int q = 0; q < 20; q++) {
            float4 o = make_float4(rtf(wt[q][0]), rtf(wt[q][1]), rtf(wt[q][2]), rtf(wt[q][3]));
            *(float4*)(g_WT + (size_t)q * PLB + wo) = o;
        }
    }
}

// ---------------- tensor-core GEMM, atom layout, 3-stage pipeline, 1 sync/stage ----------------
#define STAGE_F 8192                     // A 4096 + B 4096 floats per stage
#define SMEM_BYTES (3 * STAGE_F * 4)     // 98304

__global__ void __launch_bounds__(256, 2) gemm_mma(int mode, const float* __restrict__ b_left) {
    extern __shared__ float sm[];
    uint32_t sbase = smem_u32(sm);

    int tid = threadIdx.x;
    int z  = blockIdx.z;
    int mt = blockIdx.y;
    int nt = blockIdx.x;
    int m0 = mt * 128, n0 = nt * 128;

    int nch = (mode == 0) ? 1 : c_nch[z];
    int n_iter = nch << 4;

    int wid = tid >> 5, lane = tid & 31;
    int rb = (wid >> 1) * 32;
    int cb = (wid & 1) * 64;
    int grp = lane >> 2, tg = lane & 3;

    float acc[2][8][4];
    #pragma unroll
    for (int mi = 0; mi < 2; mi++)
        #pragma unroll
        for (int ni = 0; ni < 8; ni++)
            #pragma unroll
            for (int q = 0; q < 4; q++) acc[mi][ni][q] = 0.f;

    // ---- stateful prefetch: channel bases resolved once per 16 stages ----
    const float* pA;
    const float* pB;
    int pch = 0, pq = 0;
    auto setch = [&](int ch) {
        if (mode == 0) {
            pA = g_XP + (size_t)z * PLA;
            pB = g_WR + (size_t)c_grade[z] * PLB;
        } else {
            int ai = c_aidx[z][ch], bi = c_bidx[z][ch];
            pA = (ai < 8) ? g_XP + (size_t)ai * PLA : g_ZP + (size_t)(ai - 8) * PLA;
            pB = (bi < 4) ? g_WL + (size_t)bi * PLB : g_WT + (size_t)(bi - 4) * PLB;
        }
        pA += (size_t)mt * 4096;
        pB += (size_t)nt * 4096;
    };
    setch(0);

    uint32_t pslot_addr = sbase;          // rolling smem slot base address
    auto issue = [&]() {
        uint32_t Asm = pslot_addr;
        uint32_t Bsm = Asm + 16384;
        const float* A = pA;
        const float* B = pB;
        #pragma unroll
        for (int r = 0; r < 4; r++)
            cp16(Asm + (uint32_t)tid * 16 + r * 4096, A + tid * 4 + r * 1024);
        #pragma unroll
        for (int r = 0; r < 4; r++)
            cp16(Bsm + (uint32_t)tid * 16 + r * 4096, B + tid * 4 + r * 1024);
        asm volatile("cp.async.commit_group;" ::: "memory");
        pA += 65536;                       // next q: A tile stride = 16 tiles
        pB += 16384;                       // next q: B tile stride = 4 tiles
        pslot_addr += STAGE_F * 4;
        if (pslot_addr == sbase + 3 * STAGE_F * 4) pslot_addr = sbase;
        if (++pq == 16) { pq = 0; if (++pch < nch) setch(pch); }
    };

    issue();
    issue();

    int artA = rb >> 3;
    int brt  = cb >> 3;
    int fl = grp * 16 + tg * 4;
    const float* cslot = sm;              // rolling compute slot
    const float* smend = sm + 3 * STAGE_F;

    for (int i = 0; i < n_iter; i++) {
        if (i + 1 < n_iter) {
            asm volatile("cp.async.wait_group 1;" ::: "memory");
        } else {
            asm volatile("cp.async.wait_group 0;" ::: "memory");
        }
        __syncthreads();
        if (i + 2 < n_iter) issue();

        const float* At = cslot;
        const float* Bt = At + 4096;
        cslot += STAGE_F;
        if (cslot == smend) cslot = sm;

        #pragma unroll
        for (int kc = 0; kc < 2; kc++) {
            float4 fa[2][2];
            #pragma unroll
            for (int mi = 0; mi < 2; mi++) {
                int ar0 = artA + mi * 2;
                fa[mi][0] = *(const float4*)(At + (ar0 * 2 + kc) * 128 + fl);
                fa[mi][1] = *(const float4*)(At + ((ar0 + 1) * 2 + kc) * 128 + fl);
            }
            float4 fb[8];
            #pragma unroll
            for (int ni = 0; ni < 8; ni++)
                fb[ni] = *(const float4*)(Bt + ((brt + ni) * 2 + kc) * 128 + fl);
            #pragma unroll
            for (int mi = 0; mi < 2; mi++)
                #pragma unroll
                for (int ni = 0; ni < 8; ni++) {
                    mma_tf32(acc[mi][ni],
                             __float_as_uint(fa[mi][0].x), __float_as_uint(fa[mi][1].x),
                             __float_as_uint(fa[mi][0].y), __float_as_uint(fa[mi][1].y),
                             __float_as_uint(fb[ni].x), __float_as_uint(fb[ni].y));
                    mma_tf32(acc[mi][ni],
                             __float_as_uint(fa[mi][0].z), __float_as_uint(fa[mi][1].z),
                             __float_as_uint(fa[mi][0].w), __float_as_uint(fa[mi][1].w),
                             __float_as_uint(fb[ni].z), __float_as_uint(fb[ni].w));
                }
        }
    }

    // ---------------- epilogue ----------------
    const float RS2 = 0.70710678118654752440f;
    if (mode == 0) {
        // stage output tile (128x128, atom layout) in smem, then contiguous copy-out
        __syncthreads();
        #pragma unroll
        for (int mi = 0; mi < 2; mi++)
            #pragma unroll
            for (int h = 0; h < 2; h++) {
                int r = rb + mi * 16 + grp + h * 8;          // 0..127
                int rpart = ((r >> 3) * 2) * 128 + (r & 7) * 16;
                #pragma unroll
                for (int ni = 0; ni < 8; ni++) {
                    int c = cb + ni * 8 + 2 * tg;            // 0..126
                    #pragma unroll
                    for (int d = 0; d < 2; d++) {
                        int cc = c + d;
                        int off = (cc >> 5) * 4096 + rpart + ((cc >> 4) & 1) * 128
                                + (cc & 3) * 4 + ((cc >> 2) & 3);
                        sm[off] = acc[mi][ni][h * 2 + d];
                    }
                }
            }
        __syncthreads();
        float* XRp = g_XR + (size_t)z * PLA + ((size_t)(nt * 4) * 16 + mt) * 4096;
        #pragma unroll
        for (int t = 0; t < 4; t++) {
            float* dst = XRp + (size_t)t * 65536;
            const float* src = sm + t * 4096;
            #pragma unroll
            for (int r = 0; r < 4; r++) {
                int e = tid + (r << 8);
                *(float4*)(dst + e * 4) = *(const float4*)(src + e * 4);
            }
        }
    } else {
        float* Out = g_OUTP + (size_t)z * PLA;
        #pragma unroll
        for (int mi = 0; mi < 2; mi++)
            #pragma unroll
            for (int h = 0; h < 2; h++) {
                int row = m0 + rb + mi * 16 + grp + h * 8;
                float* dp = Out + (size_t)row * NOUT + n0 + cb;
                #pragma unroll
                for (int ni = 0; ni < 8; ni++) {
                    int col = ni * 8 + 2 * tg;
                    float v0 = acc[mi][ni][h * 2 + 0];
                    float v1 = acc[mi][ni][h * 2 + 1];
                    if (z == 0) {
                        v0 += b_left[n0 + cb + col];
                        v1 += b_left[n0 + cb + col + 1];
                    }
                    *(float2*)(dp + col) = make_float2(v0 * RS2, v1 * RS2);
                }
            }
    }
}

// ---------------- K2: gating + 44 pair channels (atom quads in/out) ----------------
__global__ void k2_pair(const float* __restrict__ norm_a) {
    int idx = blockIdx.x * blockDim.x + threadIdx.x;   // BATCH*128
    int b = idx >> 7;
    int j = idx & 127;
    int group = j >> 2, X = j & 3;
    int k0v = group * 16 + X;

    size_t qo = qbase(b, group, X, 16);
    float xv[8][4], yv[8][4];
    #pragma unroll
    for (int bl = 0; bl < 8; bl++) {
        float4 fx = *(const float4*)(g_XP + (size_t)bl * PLA + qo);
        xv[bl][0] = fx.x; xv[bl][1] = fx.y; xv[bl][2] = fx.z; xv[bl][3] = fx.w;
        float4 fy = *(const float4*)(g_XR + (size_t)bl * PLA + qo);
        yv[bl][0] = fy.x; yv[bl][1] = fy.y; yv[bl][2] = fy.z; yv[bl][3] = fy.w;
    }

    #pragma unroll
    for (int t = 0; t < 4; t++) {
        int n = k0v + 4 * t;
        float4 na = *(const float4*)(norm_a + n * 4);
        float n0 = fabsf(yv[0][t]);
        float n1 = sqrtf(yv[1][t]*yv[1][t] + yv[2][t]*yv[2][t] + yv[3][t]*yv[3][t]);
        float n2 = sqrtf(yv[4][t]*yv[4][t] + yv[5][t]*yv[5][t] + yv[6][t]*yv[6][t]);
        float n3 = fabsf(yv[7][t]);
        float s0 = 1.f / (1.f + expf(-na.x));
        float s1 = 1.f / (1.f + expf(-na.y));
        float s2 = 1.f / (1.f + expf(-na.z));
        float s3 = 1.f / (1.f + expf(-na.w));
        float i0 = 1.f / (s0 * (n0 - 1.f) + 1.f + 1e-6f);
        float i1 = 1.f / (s1 * (n1 - 1.f) + 1.f + 1e-6f);
        float i2 = 1.f / (s2 * (n2 - 1.f) + 1.f + 1e-6f);
        float i3 = 1.f / (s3 * (n3 - 1.f) + 1.f + 1e-6f);
        yv[0][t] *= i0;
        yv[1][t] *= i1; yv[2][t] *= i1; yv[3][t] *= i1;
        yv[4][t] *= i2; yv[5][t] *= i2; yv[6][t] *= i2;
        yv[7][t] *= i3;
    }

    auto emit = [&](int c, auto f) {
        float4 o = make_float4(rtf(f(0)), rtf(f(1)), rtf(f(2)), rtf(f(3)));
        *(float4*)(g_ZP + (size_t)c * PLA + qo) = o;
    };
    emit(0,  [&](int t){ return xv[0][t]*yv[0][t]; });
    emit(1,  [&](int t){ return xv[0][t]*yv[1][t]; });
    emit(2,  [&](int t){ return xv[0][t]*yv[2][t]; });
    emit(3,  [&](int t){ return xv[0][t]*yv[3][t]; });
    emit(4,  [&](int t){ return xv[0][t]*yv[4][t]; });
    emit(5,  [&](int t){ return xv[0][t]*yv[5][t]; });
    emit(6,  [&](int t){ return xv[0][t]*yv[6][t]; });
    emit(7,  [&](int t){ return xv[0][t]*yv[7][t]; });
    emit(8,  [&](int t){ return xv[1][t]*yv[1][t] + xv[2][t]*yv[2][t] + xv[3][t]*yv[3][t]; });
    emit(9,  [&](int t){ return xv[1][t]*yv[0][t]; });
    emit(10, [&](int t){ return xv[2][t]*yv[0][t]; });
    emit(11, [&](int t){ return xv[3][t]*yv[0][t]; });
    emit(12, [&](int t){ return -xv[2][t]*yv[4][t] - xv[3][t]*yv[5][t]; });
    emit(13, [&](int t){ return  xv[1][t]*yv[4][t] - xv[3][t]*yv[6][t]; });
    emit(14, [&](int t){ return  xv[1][t]*yv[5][t] + xv[2][t]*yv[6][t]; });
    emit(15, [&](int t){ return  xv[1][t]*yv[2][t] - xv[2][t]*yv[1][t]; });
    emit(16, [&](int t){ return  xv[1][t]*yv[3][t] - xv[3][t]*yv[1][t]; });
    emit(17, [&](int t){ return  xv[2][t]*yv[3][t] - xv[3][t]*yv[2][t]; });
    emit(18, [&](int t){ return  xv[3][t]*yv[7][t]; });
    emit(19, [&](int t){ return -xv[2][t]*yv[7][t]; });
    emit(20, [&](int t){ return  xv[1][t]*yv[7][t]; });
    emit(21, [&](int t){ return  xv[1][t]*yv[6][t] - xv[2][t]*yv[5][t] + xv[3][t]*yv[4][t]; });
    emit(22, [&](int t){ return -(xv[4][t]*yv[4][t] + xv[5][t]*yv[5][t] + xv[6][t]*yv[6][t]); });
    emit(23, [&](int t){ return  xv[4][t]*yv[2][t] + xv[5][t]*yv[3][t]; });
    emit(24, [&](int t){ return -xv[4][t]*yv[1][t] + xv[6][t]*yv[3][t]; });
    emit(25, [&](int t){ return -xv[5][t]*yv[1][t] - xv[6][t]*yv[2][t]; });
    emit(26, [&](int t){ return -xv[6][t]*yv[7][t]; });
    emit(27, [&](int t){ return  xv[5][t]*yv[7][t]; });
    emit(28, [&](int t){ return -xv[4][t]*yv[7][t]; });
    emit(29, [&](int t){ return  xv[4][t]*yv[0][t]; });
    emit(30, [&](int t){ return  xv[5][t]*yv[0][t]; });
    emit(31, [&](int t){ return  xv[6][t]*yv[0][t]; });
    emit(32, [&](int t){ return -xv[5][t]*yv[6][t] + xv[6][t]*yv[5][t]; });
    emit(33, [&](int t){ return  xv[4][t]*yv[6][t] - xv[6][t]*yv[4][t]; });
    emit(34, [&](int t){ return -xv[4][t]*yv[5][t] + xv[5][t]*yv[4][t]; });
    emit(35, [&](int t){ return  xv[4][t]*yv[3][t] - xv[5][t]*yv[2][t] + xv[6][t]*yv[1][t]; });
    emit(36, [&](int t){ return -xv[7][t]*yv[7][t]; });
    emit(37, [&](int t){ return -xv[7][t]*yv[6][t]; });
    emit(38, [&](int t){ return  xv[7][t]*yv[5][t]; });
    emit(39, [&](int t){ return -xv[7][t]*yv[4][t]; });
    emit(40, [&](int t){ return  xv[7][t]*yv[3][t]; });
    emit(41, [&](int t){ return -xv[7][t]*yv[2][t]; });
    emit(42, [&](int t){ return  xv[7][t]*yv[1][t]; });
    emit(43, [&](int t){ return  xv[7][t]*yv[0][t]; });
}

// ---------------- K4: planar -> interleaved output ----------------
__global__ void k4_out(float* __restrict__ out) {
    int idx = blockIdx.x * blockDim.x + threadIdx.x;   // BATCH*NOUT
    size_t o = (size_t)idx;
    float4 o0, o1;
    o0.x = g_OUTP[0*PLA + o]; o0.y = g_OUTP[1*PLA + o];
    o0.z = g_OUTP[2*PLA + o]; o0.w = g_OUTP[3*PLA + o];
    o1.x = g_OUTP[4*PLA + o]; o1.y = g_OUTP[5*PLA + o];
    o1.z = g_OUTP[6*PLA + o]; o1.w = g_OUTP[7*PLA + o];
    ((float4*)out)[o * 2 + 0] = o0;
    ((float4*)out)[o * 2 + 1] = o1;
}

// ---------------- launch ----------------
extern "C" void kernel_launch(void* const* d_in, const int* in_sizes, int n_in,
                              void* d_out, int out_size) {
    const float* x       = (const float*)d_in[0];
    const float* weight  = (const float*)d_in[1];
    const float* w_right = (const float*)d_in[2];
    const float* w_left  = (const float*)d_in[3];
    const float* b_left  = (const float*)d_in[4];
    const float* norm_a  = (const float*)d_in[5];
    float* out = (float*)d_out;

    cudaFuncSetAttribute(gemm_mma, cudaFuncAttributeMaxDynamicSharedMemorySize, SMEM_BYTES);

    int eb = (BATCH * 128) / 256;
    k0_prep<<<eb, 256>>>(x, weight, w_right, w_left);

    dim3 gg(NOUT / 128, BATCH / 128, 8);
    gemm_mma<<<gg, 256, SMEM_BYTES>>>(0, nullptr);
    k2_pair<<<eb, 256>>>(norm_a);
    gemm_mma<<<gg, 256, SMEM_BYTES>>>(1, b_left);
    k4_out<<<(BATCH * NOUT) / 256, 256>>>(out);
}

// round 9
// speedup vs baseline: 3.4270x; 1.0046x over previous
#include <cuda_runtime.h>
#include <cstdint>
#include <math.h>

#define BATCH 2048
#define NIN   512
#define NOUT  512
#define PLA ((size_t)BATCH * NIN)
#define PLB ((size_t)NOUT * NIN)

// ---------------- device scratch ----------------
// "Atom" plane layout:
//  plane = tiles of 128 rows x 32 k (4096 floats, 16KB), tile idx = (k>>5)*nR + (row>>7)
//  tile  = atoms of 8 rows x 16 k (128 floats), atom idx = ((row&127)>>3)*2 + ((k&31)>>4)
//  atom  = float off ((row&7)*4 + (k&3))*4 + ((k>>2)&3)
__device__ float g_XP[8 * BATCH * NIN];     // x planes (atom, nR=16), tf32
__device__ float g_ZP[44 * BATCH * NIN];    // pair channels (atom, nR=16), tf32
__device__ float g_XR[8 * BATCH * NIN];     // xr (atom, nR=16), fp32
__device__ float g_OUTP[8 * BATCH * NOUT];  // planar LINEAR output
__device__ float g_WR[4 * NIN * NIN];       // w_right (atom, nR=4), tf32
__device__ float g_WL[4 * NOUT * NIN];      // w_left (atom, nR=4), tf32
__device__ float g_WT[20 * NOUT * NIN];     // weight paths (atom, nR=4), tf32

__constant__ int c_grade[8] = {0,1,1,1,2,2,2,3};
__constant__ int c_nch[8] = {5,7,7,7,7,7,7,5};
__constant__ int c_zord[8] = {1,2,3,4,5,6,0,7};   // long blades first
__constant__ int c_aidx[8][7] = {
    {0, 8,16,30,44, 0, 0},
    {1, 9,17,20,31,34,45},
    {2,10,18,21,32,35,46},
    {3,11,19,22,33,36,47},
    {4,12,23,26,37,40,48},
    {5,13,24,27,38,41,49},
    {6,14,25,28,39,42,50},
    {7,15,29,43,51, 0, 0}
};
__constant__ int c_bidx[8][7] = {
    {0, 4, 8,14,20, 0, 0},
    {1, 5, 9,10,15,16,21},
    {1, 5, 9,10,15,16,21},
    {1, 5, 9,10,15,16,21},
    {2, 6,11,12,17,18,22},
    {2, 6,11,12,17,18,22},
    {2, 6,11,12,17,18,22},
    {3, 7,13,19,23, 0, 0}
};

// ---------------- helpers ----------------
__device__ __forceinline__ float rtf(float x) {
    uint32_t u;
    asm("cvt.rna.tf32.f32 %0, %1;" : "=r"(u) : "f"(x));
    return __uint_as_float(u);
}
__device__ __forceinline__ uint32_t smem_u32(const void* p) {
    uint32_t a;
    asm("{ .reg .u64 t; cvta.to.shared.u64 t, %1; cvt.u32.u64 %0, t; }" : "=r"(a) : "l"(p));
    return a;
}
__device__ __forceinline__ void mbar_init(uint32_t a, uint32_t cnt) {
    asm volatile("mbarrier.init.shared.b64 [%0], %1;" :: "r"(a), "r"(cnt) : "memory");
}
__device__ __forceinline__ void mbar_expect(uint32_t a, uint32_t tx) {
    asm volatile("mbarrier.arrive.expect_tx.shared.b64 _, [%0], %1;" :: "r"(a), "r"(tx) : "memory");
}
__device__ __forceinline__ void mbar_arrive(uint32_t a) {
    asm volatile("mbarrier.arrive.shared.b64 _, [%0];" :: "r"(a) : "memory");
}
__device__ __forceinline__ void mbar_wait(uint32_t mbar, uint32_t parity) {
    asm volatile(
        "{\n\t.reg .pred P;\n\t"
        "WL_%=:\n\t"
        "mbarrier.try_wait.parity.acquire.cta.shared::cta.b64 P, [%0], %1, 0x989680;\n\t"
        "@P bra.uni WD_%=;\n\t"
        "bra.uni WL_%=;\n\t"
        "WD_%=:\n\t}"
        :: "r"(mbar), "r"(parity) : "memory");
}
__device__ __forceinline__ void bulk_g2s(uint32_t dst, const float* src, uint32_t bytes, uint32_t mbar) {
    asm volatile(
        "cp.async.bulk.shared::cluster.global.mbarrier::complete_tx::bytes [%0], [%1], %2, [%3];"
        :: "r"(dst), "l"(src), "r"(bytes), "r"(mbar) : "memory");
}
__device__ __forceinline__ void mma_tf32(float* c, uint32_t a0, uint32_t a1, uint32_t a2, uint32_t a3,
                                         uint32_t b0, uint32_t b1) {
    asm volatile(
        "mma.sync.aligned.m16n8k8.row.col.f32.tf32.tf32.f32 "
        "{%0,%1,%2,%3}, {%4,%5,%6,%7}, {%8,%9}, {%0,%1,%2,%3};"
        : "+f"(c[0]), "+f"(c[1]), "+f"(c[2]), "+f"(c[3])
        : "r"(a0), "r"(a1), "r"(a2), "r"(a3), "r"(b0), "r"(b1));
}
#define FENCE_ASYNC() asm volatile("fence.proxy.async.shared::cta;" ::: "memory")

__device__ __forceinline__ size_t qbase(int r, int group, int X, int nR) {
    return ((size_t)((group >> 1) * nR + (r >> 7))) * 4096
         + (size_t)((((r & 127) >> 3) * 2 + (group & 1)) * 128 + ((r & 7) * 4 + X) * 4);
}

// ---------------- K0: transpose + tf32-round inputs into atom planes ----------------
__global__ void k0_prep(const float* __restrict__ x,
                        const float* __restrict__ weight,
                        const float* __restrict__ w_right,
                        const float* __restrict__ w_left) {
    int idx = blockIdx.x * blockDim.x + threadIdx.x;   // BATCH*128
    int b = idx >> 7;
    int j = idx & 127;
    int group = j >> 2, X = j & 3;
    int k0v = group * 16 + X;

    float xb[8][4];
    #pragma unroll
    for (int t = 0; t < 4; t++) {
        int k = k0v + 4 * t;
        const float4* p = (const float4*)(x + ((size_t)b * 512 + k) * 8);
        float4 f0 = p[0], f1 = p[1];
        xb[0][t] = f0.x; xb[1][t] = f0.y; xb[2][t] = f0.z; xb[3][t] = f0.w;
        xb[4][t] = f1.x; xb[5][t] = f1.y; xb[6][t] = f1.z; xb[7][t] = f1.w;
    }
    size_t xo = qbase(b, group, X, 16);
    #pragma unroll
    for (int bl = 0; bl < 8; bl++) {
        float4 o = make_float4(rtf(xb[bl][0]), rtf(xb[bl][1]), rtf(xb[bl][2]), rtf(xb[bl][3]));
        *(float4*)(g_XP + (size_t)bl * PLA + xo) = o;
    }

    if (b < NOUT) {
        int m = b;
        size_t wo = qbase(m, group, X, 4);
        float wr[4][4], wl[4][4], wt[20][4];
        #pragma unroll
        for (int t = 0; t < 4; t++) {
            int k = k0v + 4 * t;
            float4 r = ((const float4*)w_right)[(size_t)m * 512 + k];
            wr[0][t] = r.x; wr[1][t] = r.y; wr[2][t] = r.z; wr[3][t] = r.w;
            float4 l = ((const float4*)w_left)[(size_t)m * 512 + k];
            wl[0][t] = l.x; wl[1][t] = l.y; wl[2][t] = l.z; wl[3][t] = l.w;
            const float4* wp = (const float4*)(weight + ((size_t)m * 512 + k) * 20);
            #pragma unroll
            for (int q = 0; q < 5; q++) {
                float4 f = wp[q];
                wt[q*4+0][t] = f.x; wt[q*4+1][t] = f.y; wt[q*4+2][t] = f.z; wt[q*4+3][t] = f.w;
            }
        }
        #pragma unroll
        for (int g = 0; g < 4; g++) {
            float4 o = make_float4(rtf(wr[g][0]), rtf(wr[g][1]), rtf(wr[g][2]), rtf(wr[g][3]));
            *(float4*)(g_WR + (size_t)g * PLB + wo) = o;
            float4 p = make_float4(rtf(wl[g][0]), rtf(wl[g][1]), rtf(wl[g][2]), rtf(wl[g][3]));
            *(float4*)(g_WL + (size_t)g * PLB + wo) = p;
        }
        #pragma unroll
        for (int q = 0; q < 20; q++) {
            float4 o = make_float4(rtf(wt[q][0]), rtf(wt[q][1]), rtf(wt[q][2]), rtf(wt[q][3]));
            *(float4*)(g_WT + (size_t)q * PLB + wo) = o;
        }
    }
}

// ---------------- tensor-core GEMM: bulk-copy producer + mbarrier ring ----------------
#define STAGE_F 8192                     // A 4096 + B 4096 floats per slot
#define STAGE_BYTES (STAGE_F * 4)
#define SMEM_BYTES (3 * STAGE_BYTES)     // 98304

__global__ void __launch_bounds__(256, 2) gemm_mma(int mode, const float* __restrict__ b_left) {
    extern __shared__ __align__(128) float sm[];
    __shared__ __align__(8) unsigned long long bars[6];   // full0..2, empty0..2

    uint32_t sbase = smem_u32(sm);
    uint32_t barb  = smem_u32(bars);

    int tid = threadIdx.x;
    int z  = c_zord[blockIdx.z];
    int mt = blockIdx.y;
    int nt = blockIdx.x;
    int m0 = mt * 128, n0 = nt * 128;

    int nch = (mode == 0) ? 1 : c_nch[z];
    int n_iter = nch << 4;

    int wid = tid >> 5, lane = tid & 31;
    int rb = (wid >> 1) * 32;
    int cb = (wid & 1) * 64;
    int grp = lane >> 2, tg = lane & 3;

    if (tid == 0) {
        #pragma unroll
        for (int s = 0; s < 3; s++) {
            mbar_init(barb + s * 8, 1);        // full: tx-based
            mbar_init(barb + 24 + s * 8, 8);   // empty: one arrive per warp
        }
        FENCE_ASYNC();
    }
    __syncthreads();

    float acc[2][8][4];
    #pragma unroll
    for (int mi = 0; mi < 2; mi++)
        #pragma unroll
        for (int ni = 0; ni < 8; ni++)
            #pragma unroll
            for (int q = 0; q < 4; q++) acc[mi][ni][q] = 0.f;

    // ---- producer state (tid 0 only) ----
    const float* pA = nullptr;
    const float* pB = nullptr;
    int pch = 0, pq = 0;
    auto setch = [&](int ch) {
        if (mode == 0) {
            pA = g_XP + (size_t)z * PLA;
            pB = g_WR + (size_t)c_grade[z] * PLB;
        } else {
            int ai = c_aidx[z][ch], bi = c_bidx[z][ch];
            pA = (ai < 8) ? g_XP + (size_t)ai * PLA : g_ZP + (size_t)(ai - 8) * PLA;
            pB = (bi < 4) ? g_WL + (size_t)bi * PLB : g_WT + (size_t)(bi - 4) * PLB;
        }
        pA += (size_t)mt * 4096;
        pB += (size_t)nt * 4096;
    };
    auto advance = [&]() {
        pA += 65536;            // next k-chunk: A stride 16 tiles
        pB += 16384;            // next k-chunk: B stride 4 tiles
        if (++pq == 16) { pq = 0; if (++pch < nch) setch(pch); }
    };

    uint32_t pslot = sbase;     // rolling producer slot addr
    int psl = 0;                // producer slot index
    if (tid == 0) {
        setch(0);
        #pragma unroll
        for (int s = 0; s < 3; s++) {
            uint32_t fb = barb + s * 8;
            mbar_expect(fb, 32768);
            bulk_g2s(sbase + s * STAGE_BYTES, pA, 16384, fb);
            bulk_g2s(sbase + s * STAGE_BYTES + 16384, pB, 16384, fb);
            advance();
        }
    }

    const float* cslot = sm;
    int sl = 0, par = 0;        // consumer slot + parity (empty-wait parity == par too)
    int fl = grp * 16 + tg * 4;
    int artA = rb >> 3;
    int brt  = cb >> 3;

    for (int i = 0; i < n_iter; i++) {
        mbar_wait(barb + sl * 8, par);

        const float* At = cslot;
        const float* Bt = At + 4096;

        #pragma unroll
        for (int kc = 0; kc < 2; kc++) {
            float4 fa[2][2];
            #pragma unroll
            for (int mi = 0; mi < 2; mi++) {
                int ar0 = artA + mi * 2;
                fa[mi][0] = *(const float4*)(At + (ar0 * 2 + kc) * 128 + fl);
                fa[mi][1] = *(const float4*)(At + ((ar0 + 1) * 2 + kc) * 128 + fl);
            }
            float4 fb[8];
            #pragma unroll
            for (int ni = 0; ni < 8; ni++)
                fb[ni] = *(const float4*)(Bt + ((brt + ni) * 2 + kc) * 128 + fl);
            #pragma unroll
            for (int mi = 0; mi < 2; mi++)
                #pragma unroll
                for (int ni = 0; ni < 8; ni++) {
                    mma_tf32(acc[mi][ni],
                             __float_as_uint(fa[mi][0].x), __float_as_uint(fa[mi][1].x),
                             __float_as_uint(fa[mi][0].y), __float_as_uint(fa[mi][1].y),
                             __float_as_uint(fb[ni].x), __float_as_uint(fb[ni].y));
                    mma_tf32(acc[mi][ni],
                             __float_as_uint(fa[mi][0].z), __float_as_uint(fa[mi][1].z),
                             __float_as_uint(fa[mi][0].w), __float_as_uint(fa[mi][1].w),
                             __float_as_uint(fb[ni].z), __float_as_uint(fb[ni].w));
                }
        }

        __syncwarp();
        if (lane == 0) mbar_arrive(barb + 24 + sl * 8);   // empty[sl]

        if (tid == 0 && i + 3 < n_iter) {
            mbar_wait(barb + 24 + sl * 8, par);           // wait all warps done with sl
            uint32_t fb = barb + sl * 8;
            mbar_expect(fb, 32768);
            bulk_g2s(pslot, pA, 16384, fb);
            bulk_g2s(pslot + 16384, pB, 16384, fb);
            advance();
        }

        // roll
        cslot += STAGE_F;
        pslot += STAGE_BYTES;
        if (++sl == 3) { sl = 0; par ^= 1; cslot = sm; pslot = sbase; }
    }

    // ---------------- epilogue ----------------
    const float RS2 = 0.70710678118654752440f;
    if (mode == 0) {
        __syncthreads();
        #pragma unroll
        for (int mi = 0; mi < 2; mi++)
            #pragma unroll
            for (int h = 0; h < 2; h++) {
                int r = rb + mi * 16 + grp + h * 8;
                int rpart = ((r >> 3) * 2) * 128 + (r & 7) * 16;
                #pragma unroll
                for (int ni = 0; ni < 8; ni++) {
                    int c = cb + ni * 8 + 2 * tg;
                    #pragma unroll
                    for (int d = 0; d < 2; d++) {
                        int cc = c + d;
                        int off = (cc >> 5) * 4096 + rpart + ((cc >> 4) & 1) * 128
                                + (cc & 3) * 4 + ((cc >> 2) & 3);
                        sm[off] = acc[mi][ni][h * 2 + d];
                    }
                }
            }
        __syncthreads();
        float* XRp = g_XR + (size_t)z * PLA + ((size_t)(nt * 4) * 16 + mt) * 4096;
        #pragma unroll
        for (int t = 0; t < 4; t++) {
            float* dst = XRp + (size_t)t * 65536;
            const float* src = sm + t * 4096;
            #pragma unroll
            for (int r = 0; r < 4; r++) {
                int e = tid + (r << 8);
                *(float4*)(dst + e * 4) = *(const float4*)(src + e * 4);
            }
        }
    } else {
        float* Out = g_OUTP + (size_t)z * PLA;
        #pragma unroll
        for (int mi = 0; mi < 2; mi++)
            #pragma unroll
            for (int h = 0; h < 2; h++) {
                int row = m0 + rb + mi * 16 + grp + h * 8;
                float* dp = Out + (size_t)row * NOUT + n0 + cb;
                #pragma unroll
                for (int ni = 0; ni < 8; ni++) {
                    int col = ni * 8 + 2 * tg;
                    float v0 = acc[mi][ni][h * 2 + 0];
                    float v1 = acc[mi][ni][h * 2 + 1];
                    if (z == 0) {
                        v0 += b_left[n0 + cb + col];
                        v1 += b_left[n0 + cb + col + 1];
                    }
                    *(float2*)(dp + col) = make_float2(v0 * RS2, v1 * RS2);
                }
            }
    }
}

// ---------------- K2: gating + 44 pair channels (atom quads in/out) ----------------
__global__ void k2_pair(const float* __restrict__ norm_a) {
    int idx = blockIdx.x * blockDim.x + threadIdx.x;   // BATCH*128
    int b = idx >> 7;
    int j = idx & 127;
    int group = j >> 2, X = j & 3;
    int k0v = group * 16 + X;

    size_t qo = qbase(b, group, X, 16);
    float xv[8][4], yv[8][4];
    #pragma unroll
    for (int bl = 0; bl < 8; bl++) {
        float4 fx = *(const float4*)(g_XP + (size_t)bl * PLA + qo);
        xv[bl][0] = fx.x; xv[bl][1] = fx.y; xv[bl][2] = fx.z; xv[bl][3] = fx.w;
        float4 fy = *(const float4*)(g_XR + (size_t)bl * PLA + qo);
        yv[bl][0] = fy.x; yv[bl][1] = fy.y; yv[bl][2] = fy.z; yv[bl][3] = fy.w;
    }

    #pragma unroll
    for (int t = 0; t < 4; t++) {
        int n = k0v + 4 * t;
        float4 na = *(const float4*)(norm_a + n * 4);
        float n0 = fabsf(yv[0][t]);
        float n1 = sqrtf(yv[1][t]*yv[1][t] + yv[2][t]*yv[2][t] + yv[3][t]*yv[3][t]);
        float n2 = sqrtf(yv[4][t]*yv[4][t] + yv[5][t]*yv[5][t] + yv[6][t]*yv[6][t]);
        float n3 = fabsf(yv[7][t]);
        float s0 = 1.f / (1.f + expf(-na.x));
        float s1 = 1.f / (1.f + expf(-na.y));
        float s2 = 1.f / (1.f + expf(-na.z));
        float s3 = 1.f / (1.f + expf(-na.w));
        float i0 = 1.f / (s0 * (n0 - 1.f) + 1.f + 1e-6f);
        float i1 = 1.f / (s1 * (n1 - 1.f) + 1.f + 1e-6f);
        float i2 = 1.f / (s2 * (n2 - 1.f) + 1.f + 1e-6f);
        float i3 = 1.f / (s3 * (n3 - 1.f) + 1.f + 1e-6f);
        yv[0][t] *= i0;
        yv[1][t] *= i1; yv[2][t] *= i1; yv[3][t] *= i1;
        yv[4][t] *= i2; yv[5][t] *= i2; yv[6][t] *= i2;
        yv[7][t] *= i3;
    }

    auto emit = [&](int c, auto f) {
        float4 o = make_float4(rtf(f(0)), rtf(f(1)), rtf(f(2)), rtf(f(3)));
        *(float4*)(g_ZP + (size_t)c * PLA + qo) = o;
    };
    emit(0,  [&](int t){ return xv[0][t]*yv[0][t]; });
    emit(1,  [&](int t){ return xv[0][t]*yv[1][t]; });
    emit(2,  [&](int t){ return xv[0][t]*yv[2][t]; });
    emit(3,  [&](int t){ return xv[0][t]*yv[3][t]; });
    emit(4,  [&](int t){ return xv[0][t]*yv[4][t]; });
    emit(5,  [&](int t){ return xv[0][t]*yv[5][t]; });
    emit(6,  [&](int t){ return xv[0][t]*yv[6][t]; });
    emit(7,  [&](int t){ return xv[0][t]*yv[7][t]; });
    emit(8,  [&](int t){ return xv[1][t]*yv[1][t] + xv[2][t]*yv[2][t] + xv[3][t]*yv[3][t]; });
    emit(9,  [&](int t){ return xv[1][t]*yv[0][t]; });
    emit(10, [&](int t){ return xv[2][t]*yv[0][t]; });
    emit(11, [&](int t){ return xv[3][t]*yv[0][t]; });
    emit(12, [&](int t){ return -xv[2][t]*yv[4][t] - xv[3][t]*yv[5][t]; });
    emit(13, [&](int t){ return  xv[1][t]*yv[4][t] - xv[3][t]*yv[6][t]; });
    emit(14, [&](int t){ return  xv[1][t]*yv[5][t] + xv[2][t]*yv[6][t]; });
    emit(15, [&](int t){ return  xv[1][t]*yv[2][t] - xv[2][t]*yv[1][t]; });
    emit(16, [&](int t){ return  xv[1][t]*yv[3][t] - xv[3][t]*yv[1][t]; });
    emit(17, [&](int t){ return  xv[2][t]*yv[3][t] - xv[3][t]*yv[2][t]; });
    emit(18, [&](int t){ return  xv[3][t]*yv[7][t]; });
    emit(19, [&](int t){ return -xv[2][t]*yv[7][t]; });
    emit(20, [&](int t){ return  xv[1][t]*yv[7][t]; });
    emit(21, [&](int t){ return  xv[1][t]*yv[6][t] - xv[2][t]*yv[5][t] + xv[3][t]*yv[4][t]; });
    emit(22, [&](int t){ return -(xv[4][t]*yv[4][t] + xv[5][t]*yv[5][t] + xv[6][t]*yv[6][t]); });
    emit(23, [&](int t){ return  xv[4][t]*yv[2][t] + xv[5][t]*yv[3][t]; });
    emit(24, [&](int t){ return -xv[4][t]*yv[1][t] + xv[6][t]*yv[3][t]; });
    emit(25, [&](int t){ return -xv[5][t]*yv[1][t] - xv[6][t]*yv[2][t]; });
    emit(26, [&](int t){ return -xv[6][t]*yv[7][t]; });
    emit(27, [&](int t){ return  xv[5][t]*yv[7][t]; });
    emit(28, [&](int t){ return -xv[4][t]*yv[7][t]; });
    emit(29, [&](int t){ return  xv[4][t]*yv[0][t]; });
    emit(30, [&](int t){ return  xv[5][t]*yv[0][t]; });
    emit(31, [&](int t){ return  xv[6][t]*yv[0][t]; });
    emit(32, [&](int t){ return -xv[5][t]*yv[6][t] + xv[6][t]*yv[5][t]; });
    emit(33, [&](int t){ return  xv[4][t]*yv[6][t] - xv[6][t]*yv[4][t]; });
    emit(34, [&](int t){ return -xv[4][t]*yv[5][t] + xv[5][t]*yv[4][t]; });
    emit(35, [&](int t){ return  xv[4][t]*yv[3][t] - xv[5][t]*yv[2][t] + xv[6][t]*yv[1][t]; });
    emit(36, [&](int t){ return -xv[7][t]*yv[7][t]; });
    emit(37, [&](int t){ return -xv[7][t]*yv[6][t]; });
    emit(38, [&](int t){ return  xv[7][t]*yv[5][t]; });
    emit(39, [&](int t){ return -xv[7][t]*yv[4][t]; });
    emit(40, [&](int t){ return  xv[7][t]*yv[3][t]; });
    emit(41, [&](int t){ return -xv[7][t]*yv[2][t]; });
    emit(42, [&](int t){ return  xv[7][t]*yv[1][t]; });
    emit(43, [&](int t){ return  xv[7][t]*yv[0][t]; });
}

// ---------------- K4: planar -> interleaved output ----------------
__global__ void k4_out(float* __restrict__ out) {
    int idx = blockIdx.x * blockDim.x + threadIdx.x;   // BATCH*NOUT
    size_t o = (size_t)idx;
    float4 o0, o1;
    o0.x = g_OUTP[0*PLA + o]; o0.y = g_OUTP[1*PLA + o];
    o0.z = g_OUTP[2*PLA + o]; o0.w = g_OUTP[3*PLA + o];
    o1.x = g_OUTP[4*PLA + o]; o1.y = g_OUTP[5*PLA + o];
    o1.z = g_OUTP[6*PLA + o]; o1.w = g_OUTP[7*PLA + o];
    ((float4*)out)[o * 2 + 0] = o0;
    ((float4*)out)[o * 2 + 1] = o1;
}

// ---------------- launch ----------------
extern "C" void kernel_launch(void* const* d_in, const int* in_sizes, int n_in,
                              void* d_out, int out_size) {
    const float* x       = (const float*)d_in[0];
    const float* weight  = (const float*)d_in[1];
    const float* w_right = (const float*)d_in[2];
    const float* w_left  = (const float*)d_in[3];
    const float* b_left  = (const float*)d_in[4];
    const float* norm_a  = (const float*)d_in[5];
    float* out = (float*)d_out;

    cudaFuncSetAttribute(gemm_mma, cudaFuncAttributeMaxDynamicSharedMemorySize, SMEM_BYTES);

    int eb = (BATCH * 128) / 256;
    k0_prep<<<eb, 256>>>(x, weight, w_right, w_left);

    dim3 gg(NOUT / 128, BATCH / 128, 8);
    gemm_mma<<<gg, 256, SMEM_BYTES>>>(0, nullptr);
    k2_pair<<<eb, 256>>>(norm_a);
    gemm_mma<<<gg, 256, SMEM_BYTES>>>(1, b_left);
    k4_out<<<(BATCH * NOUT) / 256, 256>>>(out);
}